// round 2
// baseline (speedup 1.0000x reference)
#include <cuda_runtime.h>
#include <cuda_bf16.h>
#include <math.h>

// Problem constants
#define N_   8
#define C_   64
#define T_   256
#define VQ_  90
#define VK_  50
#define S_   4
#define L_   4
#define Tq_  252            // T - L
#define SC_  256            // S*C
#define NS_  32             // N*S
#define KS_  8              // split-K factor for scores
#define KTOT 16128          // C*Tq
#define KCHUNK 2016         // KTOT/KS_

// Derived sizes
#define QP_PER_NS  1451520  // C*Tq*VQ
#define KP_PER_NS  819200   // C*T*VK
#define VP_PER_N   819200   // C*T*VK
#define Y_PER_NS   1474560  // C*T*VQ
#define SPQ  22680          // Tq*VQ
#define SPK  12800          // T*VK
#define SPO  23040          // T*VQ
#define OUT_TOTAL 11796480  // N*C*T*VQ
#define BN_COUNT  184320    // N*T*VQ

// ---------------- scratch (device globals; no allocation allowed) ------------
__device__ float g_Qp[(long)N_*SC_*Tq_*VQ_];      // 46,448,640
__device__ float g_Kp[(long)N_*SC_*T_*VK_];       // 26,214,400
__device__ float g_Vp[(long)N_*C_*T_*VK_];        //  6,553,600
__device__ float g_part[(long)KS_*NS_*(L_+1)*VQ_*VK_]; // 5,760,000
__device__ float g_att[(long)NS_*VQ_*VK_];        // 144,000
__device__ float g_y[(long)N_*SC_*T_*VQ_];        // 47,185,920
__device__ float g_z[(long)OUT_TOTAL];
__device__ float g_d[(long)OUT_TOTAL];
__device__ float g_bnpart[2*C_*N_*2];
__device__ float g_bncoef[2*C_*2];

// ---------------- generic conv1x1 GEMM: Y[n][m][sp] = W[m][:]·X[n][:][sp]+b --
// block tile 64(m) x 128(sp), BK=16, 128 threads, 8x8 micro tile
__global__ __launch_bounds__(128)
void conv_gemm(const float* __restrict__ W, const float* __restrict__ bias,
               const float* __restrict__ X, float* __restrict__ Y,
               int M, int K, int Nsp, int ldx, long xbatch, long ybatch)
{
    const int n   = blockIdx.z;
    const int m0  = blockIdx.y * 64;
    const int sp0 = blockIdx.x * 128;
    const float* Xn = X + (long)n * xbatch;
    float* Yn = Y + (long)n * ybatch;

    __shared__ float As[16][68];
    __shared__ float Bs[16][128];

    const int tid = threadIdx.x;
    const int mt = tid >> 4;     // 0..7
    const int nt = tid & 15;     // 0..15

    float acc[8][8];
    #pragma unroll
    for (int i = 0; i < 8; i++)
        #pragma unroll
        for (int j = 0; j < 8; j++) acc[i][j] = 0.f;

    for (int k0 = 0; k0 < K; k0 += 16) {
        #pragma unroll
        for (int p = 0; p < 8; p++) {
            int idx = p * 128 + tid;
            int m = idx >> 4, kk = idx & 15;
            As[kk][m] = W[(long)(m0 + m) * K + k0 + kk];
        }
        #pragma unroll
        for (int p = 0; p < 16; p++) {
            int idx = p * 128 + tid;
            int kk = idx >> 7, j = idx & 127;
            int sp = sp0 + j;
            Bs[kk][j] = (sp < Nsp) ? Xn[(long)(k0 + kk) * ldx + sp] : 0.f;
        }
        __syncthreads();
        #pragma unroll
        for (int kk = 0; kk < 16; kk++) {
            float a[8], b[8];
            #pragma unroll
            for (int i = 0; i < 8; i++) a[i] = As[kk][mt * 8 + i];
            #pragma unroll
            for (int j = 0; j < 8; j++) b[j] = Bs[kk][nt * 8 + j];
            #pragma unroll
            for (int i = 0; i < 8; i++)
                #pragma unroll
                for (int j = 0; j < 8; j++) acc[i][j] = fmaf(a[i], b[j], acc[i][j]);
        }
        __syncthreads();
    }
    #pragma unroll
    for (int i = 0; i < 8; i++) {
        int m = m0 + mt * 8 + i;
        float bv = bias ? bias[m] : 0.f;
        #pragma unroll
        for (int j = 0; j < 8; j++) {
            int sp = sp0 + nt * 8 + j;
            if (sp < Nsp) Yn[(long)m * Nsp + sp] = acc[i][j] + bv;
        }
    }
}

// ---------------- attention scores: per (ns, l, ks) block, 96x50 tile --------
// A_l[u][v] = sum_r Qp[ns][r][u] * Kp[ns][row(r,l)][v]   (r = c*Tq + t)
__global__ __launch_bounds__(160)
void score_kernel(const float* __restrict__ Qp, const float* __restrict__ Kp,
                  float* __restrict__ part)
{
    const int ns = blockIdx.x;   // 0..31
    const int l  = blockIdx.y;   // 0..4
    const int ks = blockIdx.z;   // 0..7
    const float* Qb = Qp + (long)ns * QP_PER_NS;
    const float* Kb = Kp + (long)ns * KP_PER_NS;

    __shared__ float Qs[32][96];
    __shared__ float Ks[32][52];

    const int tid = threadIdx.x;       // 160
    const int mt = tid / 10;           // 0..15 -> u = mt*6..mt*6+5
    const int vt = tid - mt * 10;      // 0..9  -> v = vt*5..vt*5+4

    float acc[6][5];
    #pragma unroll
    for (int i = 0; i < 6; i++)
        #pragma unroll
        for (int j = 0; j < 5; j++) acc[i][j] = 0.f;

    const int r0base = ks * KCHUNK;
    for (int chunk = 0; chunk < KCHUNK / 32; chunk++) {
        const int r0 = r0base + chunk * 32;
        for (int idx = tid; idx < 32 * 96; idx += 160) {
            int kk = idx / 96, m = idx - kk * 96;
            Qs[kk][m] = (m < VQ_) ? Qb[(long)(r0 + kk) * VQ_ + m] : 0.f;
        }
        for (int idx = tid; idx < 32 * 50; idx += 160) {
            int kk = idx / 50, v = idx - kk * 50;
            int r = r0 + kk;
            int c = r / Tq_, t = r - c * Tq_;
            Ks[kk][v] = Kb[(long)(c * T_ + t + l) * VK_ + v];
        }
        __syncthreads();
        #pragma unroll 8
        for (int kk = 0; kk < 32; kk++) {
            float a[6], b[5];
            #pragma unroll
            for (int i = 0; i < 6; i++) a[i] = Qs[kk][mt * 6 + i];
            #pragma unroll
            for (int j = 0; j < 5; j++) b[j] = Ks[kk][vt * 5 + j];
            #pragma unroll
            for (int i = 0; i < 6; i++)
                #pragma unroll
                for (int j = 0; j < 5; j++) acc[i][j] = fmaf(a[i], b[j], acc[i][j]);
        }
        __syncthreads();
    }
    float* pb = part + (((long)ks * NS_ + ns) * (L_ + 1) + l) * (VQ_ * VK_);
    #pragma unroll
    for (int i = 0; i < 6; i++) {
        int u = mt * 6 + i;
        if (u < VQ_) {
            #pragma unroll
            for (int j = 0; j < 5; j++)
                pb[u * VK_ + vt * 5 + j] = acc[i][j];
        }
    }
}

// ---------------- combine lags + softmax over VK -----------------------------
__global__ __launch_bounds__(64)
void softmax_kernel(const float* __restrict__ part, float* __restrict__ att)
{
    const int row = blockIdx.x;         // ns*90 + u
    const int ns = row / VQ_;
    const int u  = row - ns * VQ_;
    const int tid = threadIdx.x;        // 64
    const float inv_scale = rsqrtf((float)KTOT);

    __shared__ float red[64];
    float val = -1e30f;
    if (tid < VK_) {
        float mx = -1e30f, sm = 0.f;
        #pragma unroll
        for (int l = 0; l <= L_; l++) {
            float s = 0.f;
            #pragma unroll
            for (int ks = 0; ks < KS_; ks++)
                s += part[(((long)ks * NS_ + ns) * (L_ + 1) + l) * (VQ_ * VK_) + u * VK_ + tid];
            mx = fmaxf(mx, s);
            sm += s;
        }
        val = 0.5f * (mx + sm * (1.0f / (L_ + 1))) * inv_scale;
    }
    red[tid] = val; __syncthreads();
    for (int s = 32; s > 0; s >>= 1) {
        if (tid < s) red[tid] = fmaxf(red[tid], red[tid + s]);
        __syncthreads();
    }
    float rmax = red[0]; __syncthreads();
    float e = (tid < VK_) ? expf(val - rmax) : 0.f;
    red[tid] = e; __syncthreads();
    for (int s = 32; s > 0; s >>= 1) {
        if (tid < s) red[tid] += red[tid + s];
        __syncthreads();
    }
    float rsum = red[0];
    if (tid < VK_) att[(long)row * VK_ + tid] = e / rsum;
}

// ---------------- y = att @ V :  Y[ns][ct][vq] = sum_vk V[n][ct][vk]*att[ns][vq][vk]
// block tile 128(ct) x 96(vq), K=50, 256 threads, 8x6 micro
__global__ __launch_bounds__(256)
void ygemm_kernel(const float* __restrict__ Vp, const float* __restrict__ att,
                  float* __restrict__ y)
{
    const int ct0 = blockIdx.x * 128;
    const int ns  = blockIdx.z;
    const int n   = ns >> 2;
    const float* A = Vp + (long)n * VP_PER_N + (long)ct0 * VK_;
    const float* B = att + (long)ns * (VQ_ * VK_);
    float* Yb = y + (long)ns * Y_PER_NS + (long)ct0 * VQ_;

    __shared__ float As[50][132];
    __shared__ float Bs[50][96];

    const int tid = threadIdx.x;
    for (int idx = tid; idx < 128 * 50; idx += 256) {
        int r = idx / 50, k = idx - r * 50;
        As[k][r] = A[idx];
    }
    for (int idx = tid; idx < 96 * 50; idx += 256) {
        int u = idx / 50, k = idx - u * 50;
        Bs[k][u] = (u < VQ_) ? B[idx] : 0.f;
    }
    __syncthreads();

    const int mt = tid >> 4;   // 0..15 -> ct micro 8
    const int nt = tid & 15;   // 0..15 -> vq micro 6
    float acc[8][6];
    #pragma unroll
    for (int i = 0; i < 8; i++)
        #pragma unroll
        for (int j = 0; j < 6; j++) acc[i][j] = 0.f;

    #pragma unroll 10
    for (int k = 0; k < 50; k++) {
        float a[8], b[6];
        #pragma unroll
        for (int i = 0; i < 8; i++) a[i] = As[k][mt * 8 + i];
        #pragma unroll
        for (int j = 0; j < 6; j++) b[j] = Bs[k][nt * 6 + j];
        #pragma unroll
        for (int i = 0; i < 8; i++)
            #pragma unroll
            for (int j = 0; j < 6; j++) acc[i][j] = fmaf(a[i], b[j], acc[i][j]);
    }
    #pragma unroll
    for (int i = 0; i < 8; i++) {
        int ct = mt * 8 + i;
        #pragma unroll
        for (int j = 0; j < 6; j++) {
            int vq = nt * 6 + j;
            if (vq < VQ_) Yb[(long)ct * VQ_ + vq] = acc[i][j];
        }
    }
}

// ---------------- batchnorm: per-(c,n,tensor) partial sums -------------------
__global__ __launch_bounds__(256)
void bn_partial(const float* __restrict__ z, const float* __restrict__ d,
                float* __restrict__ partials)
{
    const int c = blockIdx.x, n = blockIdx.y, which = blockIdx.z;
    const float* src = (which ? d : z) + (long)(n * C_ + c) * SPO;
    float s1 = 0.f, s2 = 0.f;
    for (int i = threadIdx.x; i < SPO; i += 256) {
        float v = src[i];
        s1 += v; s2 += v * v;
    }
    __shared__ float r1[256], r2[256];
    int tid = threadIdx.x;
    r1[tid] = s1; r2[tid] = s2; __syncthreads();
    for (int s = 128; s > 0; s >>= 1) {
        if (tid < s) { r1[tid] += r1[tid + s]; r2[tid] += r2[tid + s]; }
        __syncthreads();
    }
    if (tid == 0) {
        partials[((which * C_ + c) * N_ + n) * 2 + 0] = r1[0];
        partials[((which * C_ + c) * N_ + n) * 2 + 1] = r2[0];
    }
}

__global__ __launch_bounds__(128)
void bn_final(const float* __restrict__ partials,
              const float* __restrict__ gz, const float* __restrict__ bz,
              const float* __restrict__ gd, const float* __restrict__ bd,
              float* __restrict__ coef)
{
    int tid = threadIdx.x;      // 0..127: which*64 + c
    if (tid >= 128) return;
    int which = tid >> 6, c = tid & 63;
    float s1 = 0.f, s2 = 0.f;
    for (int n = 0; n < N_; n++) {
        s1 += partials[((which * C_ + c) * N_ + n) * 2 + 0];
        s2 += partials[((which * C_ + c) * N_ + n) * 2 + 1];
    }
    float inv = 1.0f / (float)BN_COUNT;
    float mean = s1 * inv;
    float var  = s2 * inv - mean * mean;
    float rstd = rsqrtf(var + 1e-5f);
    float g = which ? gd[c] : gz[c];
    float b = which ? bd[c] : bz[c];
    float a = g * rstd;
    coef[tid * 2 + 0] = a;
    coef[tid * 2 + 1] = b - mean * a;
}

// ---------------- final: leaky_relu(bn(d) + bn(z)) ---------------------------
__global__ __launch_bounds__(256)
void final_kernel(const float* __restrict__ z, const float* __restrict__ d,
                  const float* __restrict__ coef, float* __restrict__ out)
{
    long i = (long)blockIdx.x * 256 + threadIdx.x;
    if (i >= OUT_TOTAL) return;
    int c = (int)((i / SPO) & (C_ - 1));
    float az = coef[c * 2], bz_ = coef[c * 2 + 1];
    float ad = coef[(C_ + c) * 2], bd_ = coef[(C_ + c) * 2 + 1];
    float v = fmaf(az, z[i], bz_) + fmaf(ad, d[i], bd_);
    out[i] = v > 0.f ? v : 0.1f * v;
}

// ---------------- launch -----------------------------------------------------
extern "C" void kernel_launch(void* const* d_in, const int* in_sizes, int n_in,
                              void* d_out, int out_size)
{
    const float* x_q   = (const float*)d_in[0];
    const float* x_k   = (const float*)d_in[1];
    const float* x_v   = (const float*)d_in[2];
    const float* Wq    = (const float*)d_in[3];
    const float* bq    = (const float*)d_in[4];
    const float* Wk    = (const float*)d_in[5];
    const float* bk    = (const float*)d_in[6];
    const float* Wv    = (const float*)d_in[7];
    const float* bv    = (const float*)d_in[8];
    const float* Wout  = (const float*)d_in[9];
    const float* bout  = (const float*)d_in[10];
    const float* gout  = (const float*)d_in[11];
    const float* bnout = (const float*)d_in[12];
    const float* Wdown = (const float*)d_in[13];
    const float* bdown = (const float*)d_in[14];
    const float* gdown = (const float*)d_in[15];
    const float* bndwn = (const float*)d_in[16];

    float *Qp, *Kp, *Vp, *part, *att, *y, *z, *dd, *bnp, *coef;
    cudaGetSymbolAddress((void**)&Qp,   g_Qp);
    cudaGetSymbolAddress((void**)&Kp,   g_Kp);
    cudaGetSymbolAddress((void**)&Vp,   g_Vp);
    cudaGetSymbolAddress((void**)&part, g_part);
    cudaGetSymbolAddress((void**)&att,  g_att);
    cudaGetSymbolAddress((void**)&y,    g_y);
    cudaGetSymbolAddress((void**)&z,    g_z);
    cudaGetSymbolAddress((void**)&dd,   g_d);
    cudaGetSymbolAddress((void**)&bnp,  g_bnpart);
    cudaGetSymbolAddress((void**)&coef, g_bncoef);

    // projections (Q on truncated prefix, K/V full, down on full x_q)
    conv_gemm<<<dim3((SPQ + 127) / 128, 4, N_), 128>>>(Wq, bq, x_q, Qp, 256, 64, SPQ, SPO, 1474560L, 5806080L);
    conv_gemm<<<dim3((SPK + 127) / 128, 4, N_), 128>>>(Wk, bk, x_k, Kp, 256, 64, SPK, SPK, 819200L, 3276800L);
    conv_gemm<<<dim3((SPK + 127) / 128, 1, N_), 128>>>(Wv, bv, x_v, Vp, 64, 64, SPK, SPK, 819200L, 819200L);
    conv_gemm<<<dim3((SPO + 127) / 128, 1, N_), 128>>>(Wdown, bdown, x_q, dd, 64, 64, SPO, SPO, 1474560L, 1474560L);

    // multi-lag attention scores (split-K=8), then combine+softmax
    score_kernel<<<dim3(NS_, L_ + 1, KS_), 160>>>(Qp, Kp, part);
    softmax_kernel<<<NS_ * VQ_, 64>>>(part, att);

    // y = att @ V, then out projection
    ygemm_kernel<<<dim3(128, 1, NS_), 256>>>(Vp, att, y);
    conv_gemm<<<dim3((SPO + 127) / 128, 1, N_), 128>>>(Wout, bout, y, z, 64, 256, SPO, SPO, 5898240L, 1474560L);

    // batchnorm stats + fused BN/add/leaky-relu epilogue
    bn_partial<<<dim3(C_, N_, 2), 256>>>(z, dd, bnp);
    bn_final<<<1, 128>>>(bnp, gout, bnout, gdown, bndwn, coef);
    final_kernel<<<(OUT_TOTAL + 255) / 256, 256>>>(z, dd, coef, (float*)d_out);
}

// round 5
// speedup vs baseline: 1.1860x; 1.1860x over previous
#include <cuda_runtime.h>
#include <cuda_bf16.h>
#include <math.h>

// Problem constants
#define N_   8
#define C_   64
#define T_   256
#define VQ_  90
#define VK_  50
#define S_   4
#define L_   4
#define Tq_  252            // T - L
#define SC_  256            // S*C
#define NS_  32             // N*S
#define KS_  16             // split over c for scores: 4 c's per block
#define KTOT 16128          // C*Tq

// Derived sizes
#define QP_PER_NS  1451520  // C*Tq*VQ
#define KP_PER_NS  819200   // C*T*VK
#define VP_PER_N   819200   // C*T*VK
#define Y_PER_NS   1474560  // C*T*VQ
#define SPQ  22680          // Tq*VQ
#define SPK  12800          // T*VK
#define SPO  23040          // T*VQ
#define OUT_TOTAL 11796480  // N*C*T*VQ
#define BN_COUNT  184320    // N*T*VQ

typedef unsigned long long u64;

// ---- packed fp32x2 helpers (FFMA2: 2x fp32 FMA throughput on sm_103a) ------
__device__ __forceinline__ u64 splat2(float a) {
    u64 r; asm("mov.b64 %0, {%1, %1};" : "=l"(r) : "f"(a)); return r;
}
__device__ __forceinline__ u64 pack2(float x, float y) {
    u64 r; asm("mov.b64 %0, {%1, %2};" : "=l"(r) : "f"(x), "f"(y)); return r;
}
__device__ __forceinline__ void fma2(u64 &d, u64 a, u64 b) {
    asm("fma.rn.f32x2 %0, %1, %2, %0;" : "+l"(d) : "l"(a), "l"(b));
}
__device__ __forceinline__ float2 unpack2(u64 x) {
    float2 f; asm("mov.b64 {%0, %1}, %2;" : "=f"(f.x), "=f"(f.y) : "l"(x)); return f;
}

// ---------------- scratch (device globals; no allocation allowed) ------------
__device__ float g_Qp[(long)N_*SC_*Tq_*VQ_];      // 46,448,640
__device__ float g_Kp[(long)N_*SC_*T_*VK_];       // 26,214,400
__device__ float g_Vp[(long)N_*C_*T_*VK_];        //  6,553,600
__device__ float g_part[(long)KS_*NS_*(L_+1)*VQ_*VK_]; // 11,520,000
__device__ float g_att[(long)NS_*VQ_*VK_];        // 144,000
__device__ float g_y[(long)N_*SC_*T_*VQ_];        // 47,185,920
__device__ float g_z[(long)OUT_TOTAL];
__device__ float g_d[(long)OUT_TOTAL];
__device__ float g_bnpart[2*C_*N_*2];
__device__ float g_bncoef[2*C_*2];

// ---------------- generic conv1x1 GEMM: Y[n][m][sp] = W[m][:]·X[n][:][sp]+b --
// block tile 64(m) x 128(sp), BK=16, 128 threads, 8m x (4 f32x2 = 8sp) micro
__global__ __launch_bounds__(128)
void conv_gemm(const float* __restrict__ W, const float* __restrict__ bias,
               const float* __restrict__ X, float* __restrict__ Y,
               int M, int K, int Nsp, int ldx, long xbatch, long ybatch)
{
    const int n   = blockIdx.z;
    const int m0  = blockIdx.y * 64;
    const int sp0 = blockIdx.x * 128;
    const float* Xn = X + (long)n * xbatch;
    float* Yn = Y + (long)n * ybatch;

    __shared__ float As[16][68];
    __shared__ float Bs[16][128];

    const int tid = threadIdx.x;
    const int mt = tid >> 4;     // 0..7
    const int nt = tid & 15;     // 0..15

    u64 acc[8][4];
    #pragma unroll
    for (int i = 0; i < 8; i++)
        #pragma unroll
        for (int j = 0; j < 4; j++) acc[i][j] = 0ull;

    for (int k0 = 0; k0 < K; k0 += 16) {
        #pragma unroll
        for (int p = 0; p < 8; p++) {
            int idx = p * 128 + tid;
            int m = idx >> 4, kk = idx & 15;
            As[kk][m] = W[(long)(m0 + m) * K + k0 + kk];
        }
        // Bs: vectorized float4 loads (Nsp always multiple of 4)
        #pragma unroll
        for (int p = 0; p < 4; p++) {
            int idx = p * 128 + tid;
            int kk = idx >> 5, j4 = (idx & 31) * 4;
            int sp = sp0 + j4;
            float4 v = make_float4(0.f, 0.f, 0.f, 0.f);
            if (sp < Nsp) v = *(const float4*)&Xn[(long)(k0 + kk) * ldx + sp];
            *(float4*)&Bs[kk][j4] = v;
        }
        __syncthreads();
        #pragma unroll
        for (int kk = 0; kk < 16; kk++) {
            // conflict-free LDS.128 (8-lane phases), then pack to f32x2
            float4 b01 = *(const float4*)&Bs[kk][nt * 8];
            float4 b23 = *(const float4*)&Bs[kk][nt * 8 + 4];
            u64 bv[4];
            bv[0] = pack2(b01.x, b01.y); bv[1] = pack2(b01.z, b01.w);
            bv[2] = pack2(b23.x, b23.y); bv[3] = pack2(b23.z, b23.w);
            #pragma unroll
            for (int i = 0; i < 8; i++) {
                u64 av = splat2(As[kk][mt * 8 + i]);
                #pragma unroll
                for (int j = 0; j < 4; j++) fma2(acc[i][j], av, bv[j]);
            }
        }
        __syncthreads();
    }
    #pragma unroll
    for (int i = 0; i < 8; i++) {
        int m = m0 + mt * 8 + i;
        float bv = bias[m];
        #pragma unroll
        for (int j = 0; j < 4; j++) {
            int sp = sp0 + nt * 8 + 2 * j;
            if (sp < Nsp) {
                float2 r = unpack2(acc[i][j]);
                float2 o; o.x = r.x + bv; o.y = r.y + bv;
                *(float2*)&Yn[(long)m * Nsp + sp] = o;
            }
        }
    }
}

// ---------------- attention scores: ALL 5 lags per block ---------------------
// A_l[u][v] = sum_{c,t} Qp[ns][c*Tq+t][u] * Kp[ns][c*T + t+l][v]
// grid (ns=32, ks=16): each block reduces 4 c's x 252 t (7 tiles of 36).
// 384 threads: 15 u-groups (6u) x 25 v-groups (2v as one f32x2); 9 idle.
__global__ __launch_bounds__(384)
void score_kernel(const float* __restrict__ Qp, const float* __restrict__ Kp,
                  float* __restrict__ part)
{
    const int ns = blockIdx.x;   // 0..31
    const int ks = blockIdx.y;   // 0..15
    const float* Qb = Qp + (long)ns * QP_PER_NS;
    const float* Kb = Kp + (long)ns * KP_PER_NS;

    __shared__ float Qs[36][96];
    __shared__ float Ks[40][52];

    const int tid = threadIdx.x;       // 0..383
    const bool active = tid < 375;
    const int ug = tid / 25;           // 0..14  -> u = ug*6..+5
    const int vg = tid - ug * 25;      // 0..24  -> v = vg*2, vg*2+1

    u64 acc[5][6];
    #pragma unroll
    for (int l = 0; l < 5; l++)
        #pragma unroll
        for (int i = 0; i < 6; i++) acc[l][i] = 0ull;

    for (int cc = 0; cc < 4; cc++) {
        const int c = ks * 4 + cc;
        const float* Qc = Qb + (long)c * Tq_ * VQ_;
        const float* Kc = Kb + (long)c * T_ * VK_;
        for (int tt = 0; tt < 7; tt++) {
            const int t0 = tt * 36;
            // load Q tile: 36 rows x 90 (pad 96)
            for (int idx = tid; idx < 36 * 96; idx += 384) {
                int kk = idx / 96, m = idx - kk * 96;
                Qs[kk][m] = (m < VQ_) ? Qc[(long)(t0 + kk) * VQ_ + m] : 0.f;
            }
            // load K tile: 40 rows (t0..t0+39) x 50 (pad 52)
            for (int idx = tid; idx < 40 * 52; idx += 384) {
                int kk = idx / 52, v = idx - kk * 52;
                Ks[kk][v] = (v < VK_) ? Kc[(long)(t0 + kk) * VK_ + v] : 0.f;
            }
            __syncthreads();
            if (active) {
                #pragma unroll 6
                for (int kk = 0; kk < 36; kk++) {
                    u64 b[5];
                    #pragma unroll
                    for (int l = 0; l < 5; l++)
                        b[l] = *(const u64*)&Ks[kk + l][vg * 2];
                    #pragma unroll
                    for (int i = 0; i < 6; i++) {
                        u64 av = splat2(Qs[kk][ug * 6 + i]);
                        #pragma unroll
                        for (int l = 0; l < 5; l++) fma2(acc[l][i], av, b[l]);
                    }
                }
            }
            __syncthreads();
        }
    }
    if (active) {
        #pragma unroll
        for (int l = 0; l < 5; l++) {
            float* pb = part + (((long)ks * NS_ + ns) * 5 + l) * (VQ_ * VK_);
            #pragma unroll
            for (int i = 0; i < 6; i++) {
                float2 r = unpack2(acc[l][i]);
                *(float2*)&pb[(ug * 6 + i) * VK_ + vg * 2] = r;
            }
        }
    }
}

// ---------------- combine lags + softmax over VK -----------------------------
__global__ __launch_bounds__(64)
void softmax_kernel(const float* __restrict__ part, float* __restrict__ att)
{
    const int row = blockIdx.x;         // ns*90 + u
    const int ns = row / VQ_;
    const int u  = row - ns * VQ_;
    const int tid = threadIdx.x;        // 64
    const float inv_scale = rsqrtf((float)KTOT);

    __shared__ float red[64];
    float val = -1e30f;
    if (tid < VK_) {
        float mx = -1e30f, sm = 0.f;
        #pragma unroll
        for (int l = 0; l <= L_; l++) {
            float s = 0.f;
            #pragma unroll
            for (int ks = 0; ks < KS_; ks++)
                s += part[(((long)ks * NS_ + ns) * (L_ + 1) + l) * (VQ_ * VK_) + u * VK_ + tid];
            mx = fmaxf(mx, s);
            sm += s;
        }
        val = 0.5f * (mx + sm * (1.0f / (L_ + 1))) * inv_scale;
    }
    red[tid] = val; __syncthreads();
    for (int s = 32; s > 0; s >>= 1) {
        if (tid < s) red[tid] = fmaxf(red[tid], red[tid + s]);
        __syncthreads();
    }
    float rmax = red[0]; __syncthreads();
    float e = (tid < VK_) ? expf(val - rmax) : 0.f;
    red[tid] = e; __syncthreads();
    for (int s = 32; s > 0; s >>= 1) {
        if (tid < s) red[tid] += red[tid + s];
        __syncthreads();
    }
    float rsum = red[0];
    if (tid < VK_) att[(long)row * VK_ + tid] = e / rsum;
}

// ---------------- y = att @ V :  Y[ns][ct][vq] = sum_vk V[n][ct][vk]*att[ns][vq][vk]
// block tile 128(ct) x 96(vq), K=50, 256 threads, 8ct x (3 f32x2 = 6vq) micro
__global__ __launch_bounds__(256)
void ygemm_kernel(const float* __restrict__ Vp, const float* __restrict__ att,
                  float* __restrict__ y)
{
    const int ct0 = blockIdx.x * 128;
    const int ns  = blockIdx.z;
    const int n   = ns >> 2;
    const float* A = Vp + (long)n * VP_PER_N + (long)ct0 * VK_;
    const float* B = att + (long)ns * (VQ_ * VK_);
    float* Yb = y + (long)ns * Y_PER_NS + (long)ct0 * VQ_;

    __shared__ float As[50][132];
    __shared__ float Bs[50][96];

    const int tid = threadIdx.x;
    for (int idx = tid; idx < 128 * 50; idx += 256) {
        int r = idx / 50, k = idx - r * 50;
        As[k][r] = A[idx];
    }
    for (int idx = tid; idx < 96 * 50; idx += 256) {
        int u = idx / 50, k = idx - u * 50;
        Bs[k][u] = (u < VQ_) ? B[idx] : 0.f;
    }
    __syncthreads();

    const int mt = tid >> 4;   // 0..15 -> ct micro 8
    const int nt = tid & 15;   // 0..15 -> vq micro 6 (3 pairs)
    u64 acc[8][3];
    #pragma unroll
    for (int i = 0; i < 8; i++)
        #pragma unroll
        for (int j = 0; j < 3; j++) acc[i][j] = 0ull;

    #pragma unroll 10
    for (int k = 0; k < 50; k++) {
        u64 b[3];
        #pragma unroll
        for (int j = 0; j < 3; j++)
            b[j] = *(const u64*)&Bs[k][nt * 6 + 2 * j];
        #pragma unroll
        for (int i = 0; i < 8; i++) {
            u64 av = splat2(As[k][mt * 8 + i]);
            #pragma unroll
            for (int j = 0; j < 3; j++) fma2(acc[i][j], av, b[j]);
        }
    }
    #pragma unroll
    for (int i = 0; i < 8; i++) {
        int ct = mt * 8 + i;
        #pragma unroll
        for (int j = 0; j < 3; j++) {
            int vq = nt * 6 + 2 * j;
            if (vq < VQ_) {
                float2 r = unpack2(acc[i][j]);
                *(float2*)&Yb[(long)ct * VQ_ + vq] = r;
            }
        }
    }
}

// ---------------- batchnorm: per-(c,n,tensor) partial sums -------------------
__global__ __launch_bounds__(256)
void bn_partial(const float* __restrict__ z, const float* __restrict__ d,
                float* __restrict__ partials)
{
    const int c = blockIdx.x, n = blockIdx.y, which = blockIdx.z;
    const float* src = (which ? d : z) + (long)(n * C_ + c) * SPO;
    float s1 = 0.f, s2 = 0.f;
    for (int i = threadIdx.x; i < SPO; i += 256) {
        float v = src[i];
        s1 += v; s2 += v * v;
    }
    __shared__ float r1[256], r2[256];
    int tid = threadIdx.x;
    r1[tid] = s1; r2[tid] = s2; __syncthreads();
    for (int s = 128; s > 0; s >>= 1) {
        if (tid < s) { r1[tid] += r1[tid + s]; r2[tid] += r2[tid + s]; }
        __syncthreads();
    }
    if (tid == 0) {
        partials[((which * C_ + c) * N_ + n) * 2 + 0] = r1[0];
        partials[((which * C_ + c) * N_ + n) * 2 + 1] = r2[0];
    }
}

__global__ __launch_bounds__(128)
void bn_final(const float* __restrict__ partials,
              const float* __restrict__ gz, const float* __restrict__ bz,
              const float* __restrict__ gd, const float* __restrict__ bd,
              float* __restrict__ coef)
{
    int tid = threadIdx.x;      // 0..127: which*64 + c
    if (tid >= 128) return;
    int which = tid >> 6, c = tid & 63;
    float s1 = 0.f, s2 = 0.f;
    for (int n = 0; n < N_; n++) {
        s1 += partials[((which * C_ + c) * N_ + n) * 2 + 0];
        s2 += partials[((which * C_ + c) * N_ + n) * 2 + 1];
    }
    float inv = 1.0f / (float)BN_COUNT;
    float mean = s1 * inv;
    float var  = s2 * inv - mean * mean;
    float rstd = rsqrtf(var + 1e-5f);
    float g = which ? gd[c] : gz[c];
    float b = which ? bd[c] : bz[c];
    float a = g * rstd;
    coef[tid * 2 + 0] = a;
    coef[tid * 2 + 1] = b - mean * a;
}

// ---------------- final: leaky_relu(bn(d) + bn(z)) ---------------------------
__global__ __launch_bounds__(256)
void final_kernel(const float* __restrict__ z, const float* __restrict__ d,
                  const float* __restrict__ coef, float* __restrict__ out)
{
    long i = (long)blockIdx.x * 256 + threadIdx.x;
    if (i >= OUT_TOTAL) return;
    int c = (int)((i / SPO) & (C_ - 1));
    float az = coef[c * 2], bz_ = coef[c * 2 + 1];
    float ad = coef[(C_ + c) * 2], bd_ = coef[(C_ + c) * 2 + 1];
    float v = fmaf(az, z[i], bz_) + fmaf(ad, d[i], bd_);
    out[i] = v > 0.f ? v : 0.1f * v;
}

// ---------------- launch -----------------------------------------------------
extern "C" void kernel_launch(void* const* d_in, const int* in_sizes, int n_in,
                              void* d_out, int out_size)
{
    const float* x_q   = (const float*)d_in[0];
    const float* x_k   = (const float*)d_in[1];
    const float* x_v   = (const float*)d_in[2];
    const float* Wq    = (const float*)d_in[3];
    const float* bq    = (const float*)d_in[4];
    const float* Wk    = (const float*)d_in[5];
    const float* bk    = (const float*)d_in[6];
    const float* Wv    = (const float*)d_in[7];
    const float* bv    = (const float*)d_in[8];
    const float* Wout  = (const float*)d_in[9];
    const float* bout  = (const float*)d_in[10];
    const float* gout  = (const float*)d_in[11];
    const float* bnout = (const float*)d_in[12];
    const float* Wdown = (const float*)d_in[13];
    const float* bdown = (const float*)d_in[14];
    const float* gdown = (const float*)d_in[15];
    const float* bndwn = (const float*)d_in[16];

    float *Qp, *Kp, *Vp, *part, *att, *y, *z, *dd, *bnp, *coef;
    cudaGetSymbolAddress((void**)&Qp,   g_Qp);
    cudaGetSymbolAddress((void**)&Kp,   g_Kp);
    cudaGetSymbolAddress((void**)&Vp,   g_Vp);
    cudaGetSymbolAddress((void**)&part, g_part);
    cudaGetSymbolAddress((void**)&att,  g_att);
    cudaGetSymbolAddress((void**)&y,    g_y);
    cudaGetSymbolAddress((void**)&z,    g_z);
    cudaGetSymbolAddress((void**)&dd,   g_d);
    cudaGetSymbolAddress((void**)&bnp,  g_bnpart);
    cudaGetSymbolAddress((void**)&coef, g_bncoef);

    // projections (Q on truncated prefix, K/V full, down on full x_q)
    conv_gemm<<<dim3((SPQ + 127) / 128, 4, N_), 128>>>(Wq, bq, x_q, Qp, 256, 64, SPQ, SPO, 1474560L, 5806080L);
    conv_gemm<<<dim3((SPK + 127) / 128, 4, N_), 128>>>(Wk, bk, x_k, Kp, 256, 64, SPK, SPK, 819200L, 3276800L);
    conv_gemm<<<dim3((SPK + 127) / 128, 1, N_), 128>>>(Wv, bv, x_v, Vp, 64, 64, SPK, SPK, 819200L, 819200L);
    conv_gemm<<<dim3((SPO + 127) / 128, 1, N_), 128>>>(Wdown, bdown, x_q, dd, 64, 64, SPO, SPO, 1474560L, 1474560L);

    // multi-lag attention scores (all 5 lags fused per block, split over c)
    score_kernel<<<dim3(NS_, KS_), 384>>>(Qp, Kp, part);
    softmax_kernel<<<NS_ * VQ_, 64>>>(part, att);

    // y = att @ V, then out projection
    ygemm_kernel<<<dim3(128, 1, NS_), 256>>>(Vp, att, y);
    conv_gemm<<<dim3((SPO + 127) / 128, 1, N_), 128>>>(Wout, bout, y, z, 64, 256, SPO, SPO, 5898240L, 1474560L);

    // batchnorm stats + fused BN/add/leaky-relu epilogue
    bn_partial<<<dim3(C_, N_, 2), 256>>>(z, dd, bnp);
    bn_final<<<1, 128>>>(bnp, gout, bnout, gdown, bndwn, coef);
    final_kernel<<<(OUT_TOTAL + 255) / 256, 256>>>(z, dd, coef, (float*)d_out);
}

// round 6
// speedup vs baseline: 1.1866x; 1.0006x over previous
#include <cuda_runtime.h>
#include <cuda_bf16.h>
#include <math.h>

// Problem constants
#define N_   8
#define C_   64
#define T_   256
#define VQ_  90
#define VK_  50
#define S_   4
#define L_   4
#define Tq_  252            // T - L
#define SC_  256            // S*C
#define NS_  32             // N*S
#define KS_  16             // split over c for scores: 4 c's per block
#define KTOT 16128          // C*Tq

// Derived sizes
#define QP_PER_NS  1451520  // C*Tq*VQ
#define KP_PER_NS  819200   // C*T*VK
#define VP_PER_N   819200   // C*T*VK
#define Y_PER_NS   1474560  // C*T*VQ
#define SPQ  22680          // Tq*VQ
#define SPK  12800          // T*VK
#define SPO  23040          // T*VQ
#define OUT_TOTAL 11796480  // N*C*T*VQ
#define BN_COUNT  184320    // N*T*VQ

typedef unsigned long long u64;

// ---- packed fp32x2 helpers (FFMA2: 2x fp32 FMA throughput on sm_103a) ------
__device__ __forceinline__ u64 splat2(float a) {
    u64 r; asm("mov.b64 %0, {%1, %1};" : "=l"(r) : "f"(a)); return r;
}
__device__ __forceinline__ u64 pack2(float x, float y) {
    u64 r; asm("mov.b64 %0, {%1, %2};" : "=l"(r) : "f"(x), "f"(y)); return r;
}
__device__ __forceinline__ void fma2(u64 &d, u64 a, u64 b) {
    asm("fma.rn.f32x2 %0, %1, %2, %0;" : "+l"(d) : "l"(a), "l"(b));
}
__device__ __forceinline__ float2 unpack2(u64 x) {
    float2 f; asm("mov.b64 {%0, %1}, %2;" : "=f"(f.x), "=f"(f.y) : "l"(x)); return f;
}

// ---------------- scratch (device globals; no allocation allowed) ------------
__device__ float g_Qp[(long)N_*SC_*Tq_*VQ_];      // 46,448,640
__device__ float g_Kp[(long)N_*SC_*T_*VK_];       // 26,214,400
__device__ float g_Vp[(long)N_*C_*T_*VK_];        //  6,553,600
__device__ float g_part[(long)KS_*NS_*(L_+1)*VQ_*VK_]; // 11,520,000
__device__ float g_att[(long)NS_*VQ_*VK_];        // 144,000
__device__ float g_y[(long)N_*SC_*T_*VQ_];        // 47,185,920
__device__ float g_z[(long)OUT_TOTAL];
__device__ float g_d[(long)OUT_TOTAL];
__device__ float g_bnpart[2*C_*N_*2];
__device__ float g_bncoef[2*C_*2];

// ---------------- generic conv1x1 GEMM: Y[n][m][sp] = W[m][:]·X[n][:][sp]+b --
// block tile 64(m) x 128(sp), BK=16, 128 threads, 8m x (4 f32x2 = 8sp) micro
__global__ __launch_bounds__(128)
void conv_gemm(const float* __restrict__ W, const float* __restrict__ bias,
               const float* __restrict__ X, float* __restrict__ Y,
               int M, int K, int Nsp, int ldx, long xbatch, long ybatch)
{
    const int n   = blockIdx.z;
    const int m0  = blockIdx.y * 64;
    const int sp0 = blockIdx.x * 128;
    const float* Xn = X + (long)n * xbatch;
    float* Yn = Y + (long)n * ybatch;

    __shared__ float As[16][68];
    __shared__ float Bs[16][128];

    const int tid = threadIdx.x;
    const int mt = tid >> 4;     // 0..7
    const int nt = tid & 15;     // 0..15

    u64 acc[8][4];
    #pragma unroll
    for (int i = 0; i < 8; i++)
        #pragma unroll
        for (int j = 0; j < 4; j++) acc[i][j] = 0ull;

    for (int k0 = 0; k0 < K; k0 += 16) {
        #pragma unroll
        for (int p = 0; p < 8; p++) {
            int idx = p * 128 + tid;
            int m = idx >> 4, kk = idx & 15;
            As[kk][m] = W[(long)(m0 + m) * K + k0 + kk];
        }
        // Bs: vectorized float4 loads (Nsp always multiple of 4)
        #pragma unroll
        for (int p = 0; p < 4; p++) {
            int idx = p * 128 + tid;
            int kk = idx >> 5, j4 = (idx & 31) * 4;
            int sp = sp0 + j4;
            float4 v = make_float4(0.f, 0.f, 0.f, 0.f);
            if (sp < Nsp) v = *(const float4*)&Xn[(long)(k0 + kk) * ldx + sp];
            *(float4*)&Bs[kk][j4] = v;
        }
        __syncthreads();
        #pragma unroll
        for (int kk = 0; kk < 16; kk++) {
            // conflict-free LDS.128 (8-lane phases), then pack to f32x2
            float4 b01 = *(const float4*)&Bs[kk][nt * 8];
            float4 b23 = *(const float4*)&Bs[kk][nt * 8 + 4];
            u64 bv[4];
            bv[0] = pack2(b01.x, b01.y); bv[1] = pack2(b01.z, b01.w);
            bv[2] = pack2(b23.x, b23.y); bv[3] = pack2(b23.z, b23.w);
            #pragma unroll
            for (int i = 0; i < 8; i++) {
                u64 av = splat2(As[kk][mt * 8 + i]);
                #pragma unroll
                for (int j = 0; j < 4; j++) fma2(acc[i][j], av, bv[j]);
            }
        }
        __syncthreads();
    }
    #pragma unroll
    for (int i = 0; i < 8; i++) {
        int m = m0 + mt * 8 + i;
        float bv = bias[m];
        #pragma unroll
        for (int j = 0; j < 4; j++) {
            int sp = sp0 + nt * 8 + 2 * j;
            if (sp < Nsp) {
                float2 r = unpack2(acc[i][j]);
                float2 o; o.x = r.x + bv; o.y = r.y + bv;
                *(float2*)&Yn[(long)m * Nsp + sp] = o;
            }
        }
    }
}

// ---------------- attention scores: ALL 5 lags per block ---------------------
// A_l[u][v] = sum_{c,t} Qp[ns][c*Tq+t][u] * Kp[ns][c*T + t+l][v]
// grid (ns=32, ks=16): each block reduces 4 c's x 252 t (7 tiles of 36).
// 384 threads: 15 u-groups (6u) x 25 v-groups (2v as one f32x2); 9 idle.
__global__ __launch_bounds__(384)
void score_kernel(const float* __restrict__ Qp, const float* __restrict__ Kp,
                  float* __restrict__ part)
{
    const int ns = blockIdx.x;   // 0..31
    const int ks = blockIdx.y;   // 0..15
    const float* Qb = Qp + (long)ns * QP_PER_NS;
    const float* Kb = Kp + (long)ns * KP_PER_NS;

    __shared__ float Qs[36][96];
    __shared__ float Ks[40][52];

    const int tid = threadIdx.x;       // 0..383
    const bool active = tid < 375;
    const int ug = tid / 25;           // 0..14  -> u = ug*6..+5
    const int vg = tid - ug * 25;      // 0..24  -> v = vg*2, vg*2+1

    u64 acc[5][6];
    #pragma unroll
    for (int l = 0; l < 5; l++)
        #pragma unroll
        for (int i = 0; i < 6; i++) acc[l][i] = 0ull;

    for (int cc = 0; cc < 4; cc++) {
        const int c = ks * 4 + cc;
        const float* Qc = Qb + (long)c * Tq_ * VQ_;
        const float* Kc = Kb + (long)c * T_ * VK_;
        for (int tt = 0; tt < 7; tt++) {
            const int t0 = tt * 36;
            // load Q tile: 36 rows x 90 (pad 96)
            for (int idx = tid; idx < 36 * 96; idx += 384) {
                int kk = idx / 96, m = idx - kk * 96;
                Qs[kk][m] = (m < VQ_) ? Qc[(long)(t0 + kk) * VQ_ + m] : 0.f;
            }
            // load K tile: 40 rows (t0..t0+39) x 50 (pad 52)
            for (int idx = tid; idx < 40 * 52; idx += 384) {
                int kk = idx / 52, v = idx - kk * 52;
                Ks[kk][v] = (v < VK_) ? Kc[(long)(t0 + kk) * VK_ + v] : 0.f;
            }
            __syncthreads();
            if (active) {
                #pragma unroll 6
                for (int kk = 0; kk < 36; kk++) {
                    u64 b[5];
                    #pragma unroll
                    for (int l = 0; l < 5; l++)
                        b[l] = *(const u64*)&Ks[kk + l][vg * 2];
                    #pragma unroll
                    for (int i = 0; i < 6; i++) {
                        u64 av = splat2(Qs[kk][ug * 6 + i]);
                        #pragma unroll
                        for (int l = 0; l < 5; l++) fma2(acc[l][i], av, b[l]);
                    }
                }
            }
            __syncthreads();
        }
    }
    if (active) {
        #pragma unroll
        for (int l = 0; l < 5; l++) {
            float* pb = part + (((long)ks * NS_ + ns) * 5 + l) * (VQ_ * VK_);
            #pragma unroll
            for (int i = 0; i < 6; i++) {
                float2 r = unpack2(acc[l][i]);
                *(float2*)&pb[(ug * 6 + i) * VK_ + vg * 2] = r;
            }
        }
    }
}

// ---------------- combine lags + softmax over VK -----------------------------
__global__ __launch_bounds__(64)
void softmax_kernel(const float* __restrict__ part, float* __restrict__ att)
{
    const int row = blockIdx.x;         // ns*90 + u
    const int ns = row / VQ_;
    const int u  = row - ns * VQ_;
    const int tid = threadIdx.x;        // 64
    const float inv_scale = rsqrtf((float)KTOT);

    __shared__ float red[64];
    float val = -1e30f;
    if (tid < VK_) {
        float mx = -1e30f, sm = 0.f;
        #pragma unroll
        for (int l = 0; l <= L_; l++) {
            float s = 0.f;
            #pragma unroll
            for (int ks = 0; ks < KS_; ks++)
                s += part[(((long)ks * NS_ + ns) * (L_ + 1) + l) * (VQ_ * VK_) + u * VK_ + tid];
            mx = fmaxf(mx, s);
            sm += s;
        }
        val = 0.5f * (mx + sm * (1.0f / (L_ + 1))) * inv_scale;
    }
    red[tid] = val; __syncthreads();
    for (int s = 32; s > 0; s >>= 1) {
        if (tid < s) red[tid] = fmaxf(red[tid], red[tid + s]);
        __syncthreads();
    }
    float rmax = red[0]; __syncthreads();
    float e = (tid < VK_) ? expf(val - rmax) : 0.f;
    red[tid] = e; __syncthreads();
    for (int s = 32; s > 0; s >>= 1) {
        if (tid < s) red[tid] += red[tid + s];
        __syncthreads();
    }
    float rsum = red[0];
    if (tid < VK_) att[(long)row * VK_ + tid] = e / rsum;
}

// ---------------- y = att @ V :  Y[ns][ct][vq] = sum_vk V[n][ct][vk]*att[ns][vq][vk]
// block tile 128(ct) x 96(vq), K=50, 256 threads, 8ct x (3 f32x2 = 6vq) micro
__global__ __launch_bounds__(256)
void ygemm_kernel(const float* __restrict__ Vp, const float* __restrict__ att,
                  float* __restrict__ y)
{
    const int ct0 = blockIdx.x * 128;
    const int ns  = blockIdx.z;
    const int n   = ns >> 2;
    const float* A = Vp + (long)n * VP_PER_N + (long)ct0 * VK_;
    const float* B = att + (long)ns * (VQ_ * VK_);
    float* Yb = y + (long)ns * Y_PER_NS + (long)ct0 * VQ_;

    __shared__ float As[50][132];
    __shared__ float Bs[50][96];

    const int tid = threadIdx.x;
    for (int idx = tid; idx < 128 * 50; idx += 256) {
        int r = idx / 50, k = idx - r * 50;
        As[k][r] = A[idx];
    }
    for (int idx = tid; idx < 96 * 50; idx += 256) {
        int u = idx / 50, k = idx - u * 50;
        Bs[k][u] = (u < VQ_) ? B[idx] : 0.f;
    }
    __syncthreads();

    const int mt = tid >> 4;   // 0..15 -> ct micro 8
    const int nt = tid & 15;   // 0..15 -> vq micro 6 (3 pairs)
    u64 acc[8][3];
    #pragma unroll
    for (int i = 0; i < 8; i++)
        #pragma unroll
        for (int j = 0; j < 3; j++) acc[i][j] = 0ull;

    #pragma unroll 10
    for (int k = 0; k < 50; k++) {
        u64 b[3];
        #pragma unroll
        for (int j = 0; j < 3; j++)
            b[j] = *(const u64*)&Bs[k][nt * 6 + 2 * j];
        #pragma unroll
        for (int i = 0; i < 8; i++) {
            u64 av = splat2(As[k][mt * 8 + i]);
            #pragma unroll
            for (int j = 0; j < 3; j++) fma2(acc[i][j], av, b[j]);
        }
    }
    #pragma unroll
    for (int i = 0; i < 8; i++) {
        int ct = mt * 8 + i;
        #pragma unroll
        for (int j = 0; j < 3; j++) {
            int vq = nt * 6 + 2 * j;
            if (vq < VQ_) {
                float2 r = unpack2(acc[i][j]);
                *(float2*)&Yb[(long)ct * VQ_ + vq] = r;
            }
        }
    }
}

// ---------------- batchnorm: per-(c,n,tensor) partial sums -------------------
__global__ __launch_bounds__(256)
void bn_partial(const float* __restrict__ z, const float* __restrict__ d,
                float* __restrict__ partials)
{
    const int c = blockIdx.x, n = blockIdx.y, which = blockIdx.z;
    const float* src = (which ? d : z) + (long)(n * C_ + c) * SPO;
    float s1 = 0.f, s2 = 0.f;
    for (int i = threadIdx.x; i < SPO; i += 256) {
        float v = src[i];
        s1 += v; s2 += v * v;
    }
    __shared__ float r1[256], r2[256];
    int tid = threadIdx.x;
    r1[tid] = s1; r2[tid] = s2; __syncthreads();
    for (int s = 128; s > 0; s >>= 1) {
        if (tid < s) { r1[tid] += r1[tid + s]; r2[tid] += r2[tid + s]; }
        __syncthreads();
    }
    if (tid == 0) {
        partials[((which * C_ + c) * N_ + n) * 2 + 0] = r1[0];
        partials[((which * C_ + c) * N_ + n) * 2 + 1] = r2[0];
    }
}

__global__ __launch_bounds__(128)
void bn_final(const float* __restrict__ partials,
              const float* __restrict__ gz, const float* __restrict__ bz,
              const float* __restrict__ gd, const float* __restrict__ bd,
              float* __restrict__ coef)
{
    int tid = threadIdx.x;      // 0..127: which*64 + c
    if (tid >= 128) return;
    int which = tid >> 6, c = tid & 63;
    float s1 = 0.f, s2 = 0.f;
    for (int n = 0; n < N_; n++) {
        s1 += partials[((which * C_ + c) * N_ + n) * 2 + 0];
        s2 += partials[((which * C_ + c) * N_ + n) * 2 + 1];
    }
    float inv = 1.0f / (float)BN_COUNT;
    float mean = s1 * inv;
    float var  = s2 * inv - mean * mean;
    float rstd = rsqrtf(var + 1e-5f);
    float g = which ? gd[c] : gz[c];
    float b = which ? bd[c] : bz[c];
    float a = g * rstd;
    coef[tid * 2 + 0] = a;
    coef[tid * 2 + 1] = b - mean * a;
}

// ---------------- final: leaky_relu(bn(d) + bn(z)) ---------------------------
__global__ __launch_bounds__(256)
void final_kernel(const float* __restrict__ z, const float* __restrict__ d,
                  const float* __restrict__ coef, float* __restrict__ out)
{
    long i = (long)blockIdx.x * 256 + threadIdx.x;
    if (i >= OUT_TOTAL) return;
    int c = (int)((i / SPO) & (C_ - 1));
    float az = coef[c * 2], bz_ = coef[c * 2 + 1];
    float ad = coef[(C_ + c) * 2], bd_ = coef[(C_ + c) * 2 + 1];
    float v = fmaf(az, z[i], bz_) + fmaf(ad, d[i], bd_);
    out[i] = v > 0.f ? v : 0.1f * v;
}

// ---------------- launch -----------------------------------------------------
extern "C" void kernel_launch(void* const* d_in, const int* in_sizes, int n_in,
                              void* d_out, int out_size)
{
    const float* x_q   = (const float*)d_in[0];
    const float* x_k   = (const float*)d_in[1];
    const float* x_v   = (const float*)d_in[2];
    const float* Wq    = (const float*)d_in[3];
    const float* bq    = (const float*)d_in[4];
    const float* Wk    = (const float*)d_in[5];
    const float* bk    = (const float*)d_in[6];
    const float* Wv    = (const float*)d_in[7];
    const float* bv    = (const float*)d_in[8];
    const float* Wout  = (const float*)d_in[9];
    const float* bout  = (const float*)d_in[10];
    const float* gout  = (const float*)d_in[11];
    const float* bnout = (const float*)d_in[12];
    const float* Wdown = (const float*)d_in[13];
    const float* bdown = (const float*)d_in[14];
    const float* gdown = (const float*)d_in[15];
    const float* bndwn = (const float*)d_in[16];

    float *Qp, *Kp, *Vp, *part, *att, *y, *z, *dd, *bnp, *coef;
    cudaGetSymbolAddress((void**)&Qp,   g_Qp);
    cudaGetSymbolAddress((void**)&Kp,   g_Kp);
    cudaGetSymbolAddress((void**)&Vp,   g_Vp);
    cudaGetSymbolAddress((void**)&part, g_part);
    cudaGetSymbolAddress((void**)&att,  g_att);
    cudaGetSymbolAddress((void**)&y,    g_y);
    cudaGetSymbolAddress((void**)&z,    g_z);
    cudaGetSymbolAddress((void**)&dd,   g_d);
    cudaGetSymbolAddress((void**)&bnp,  g_bnpart);
    cudaGetSymbolAddress((void**)&coef, g_bncoef);

    // projections (Q on truncated prefix, K/V full, down on full x_q)
    conv_gemm<<<dim3((SPQ + 127) / 128, 4, N_), 128>>>(Wq, bq, x_q, Qp, 256, 64, SPQ, SPO, 1474560L, 5806080L);
    conv_gemm<<<dim3((SPK + 127) / 128, 4, N_), 128>>>(Wk, bk, x_k, Kp, 256, 64, SPK, SPK, 819200L, 3276800L);
    conv_gemm<<<dim3((SPK + 127) / 128, 1, N_), 128>>>(Wv, bv, x_v, Vp, 64, 64, SPK, SPK, 819200L, 819200L);
    conv_gemm<<<dim3((SPO + 127) / 128, 1, N_), 128>>>(Wdown, bdown, x_q, dd, 64, 64, SPO, SPO, 1474560L, 1474560L);

    // multi-lag attention scores (all 5 lags fused per block, split over c)
    score_kernel<<<dim3(NS_, KS_), 384>>>(Qp, Kp, part);
    softmax_kernel<<<NS_ * VQ_, 64>>>(part, att);

    // y = att @ V, then out projection
    ygemm_kernel<<<dim3(128, 1, NS_), 256>>>(Vp, att, y);
    conv_gemm<<<dim3((SPO + 127) / 128, 1, N_), 128>>>(Wout, bout, y, z, 64, 256, SPO, SPO, 5898240L, 1474560L);

    // batchnorm stats + fused BN/add/leaky-relu epilogue
    bn_partial<<<dim3(C_, N_, 2), 256>>>(z, dd, bnp);
    bn_final<<<1, 128>>>(bnp, gout, bnout, gdown, bndwn, coef);
    final_kernel<<<(OUT_TOTAL + 255) / 256, 256>>>(z, dd, coef, (float*)d_out);
}

// round 9
// speedup vs baseline: 1.2785x; 1.0774x over previous
#include <cuda_runtime.h>
#include <cuda_bf16.h>
#include <math.h>

#define N_   8
#define C_   64
#define T_   256
#define VQ_  90
#define VK_  50
#define S_   4
#define L_   4
#define Tq_  252
#define SC_  256
#define NS_  32
#define KSPLIT 4
#define KTOT 16128

#define KP_PER_NS  819200
#define VP_PER_N   819200
#define Y_PER_NS   1474560
#define SPQ  22680
#define SPK  12800
#define SPO  23040
#define OUT_TOTAL 11796480
#define BN_COUNT  184320

typedef unsigned long long u64;
typedef unsigned int u32;

// ---- packed fp32x2 helpers --------------------------------------------------
__device__ __forceinline__ u64 splat2(float a) {
    u64 r; asm("mov.b64 %0, {%1, %1};" : "=l"(r) : "f"(a)); return r;
}
__device__ __forceinline__ u64 pack2(float x, float y) {
    u64 r; asm("mov.b64 %0, {%1, %2};" : "=l"(r) : "f"(x), "f"(y)); return r;
}
__device__ __forceinline__ void fma2(u64 &d, u64 a, u64 b) {
    asm("fma.rn.f32x2 %0, %1, %2, %0;" : "+l"(d) : "l"(a), "l"(b));
}
__device__ __forceinline__ float2 unpack2(u64 x) {
    float2 f; asm("mov.b64 {%0, %1}, %2;" : "=f"(f.x), "=f"(f.y) : "l"(x)); return f;
}

// ---- tf32 mma.sync helpers (base PTX, works on compute_103) -----------------
__device__ __forceinline__ u32 tf32u(float x) {
    u32 r; asm("cvt.rna.tf32.f32 %0, %1;" : "=r"(r) : "f"(x)); return r;
}
__device__ __forceinline__ void mma8(float* c, const u32* a, const u32* b) {
    asm volatile("mma.sync.aligned.m16n8k8.row.col.f32.tf32.tf32.f32 "
        "{%0,%1,%2,%3}, {%4,%5,%6,%7}, {%8,%9}, {%0,%1,%2,%3};"
        : "+f"(c[0]), "+f"(c[1]), "+f"(c[2]), "+f"(c[3])
        : "r"(a[0]), "r"(a[1]), "r"(a[2]), "r"(a[3]), "r"(b[0]), "r"(b[1]));
}

// ---------------- scratch ----------------------------------------------------
__device__ float g_Qp[(long)N_*SC_*Tq_*VQ_];
__device__ float g_Kp[(long)N_*SC_*T_*VK_];
__device__ float g_Vp[(long)N_*C_*T_*VK_];
__device__ float g_part[(long)KSPLIT*NS_*(L_+1)*VQ_*VK_];
__device__ float g_att[(long)NS_*VQ_*VK_];
__device__ float g_y[(long)N_*SC_*T_*VQ_];
__device__ float g_z[(long)OUT_TOTAL];
__device__ float g_d[(long)OUT_TOTAL];
__device__ float g_bnpart[2*C_*N_*2];
__device__ float g_bncoef[2*C_*2];

// ---------------- generic conv1x1 GEMM (unchanged, known-good) ---------------
__global__ __launch_bounds__(128)
void conv_gemm(const float* __restrict__ W, const float* __restrict__ bias,
               const float* __restrict__ X, float* __restrict__ Y,
               int M, int K, int Nsp, int ldx, long xbatch, long ybatch)
{
    const int n   = blockIdx.z;
    const int m0  = blockIdx.y * 64;
    const int sp0 = blockIdx.x * 128;
    const float* Xn = X + (long)n * xbatch;
    float* Yn = Y + (long)n * ybatch;

    __shared__ float As[16][68];
    __shared__ float Bs[16][128];

    const int tid = threadIdx.x;
    const int mt = tid >> 4;
    const int nt = tid & 15;

    u64 acc[8][4];
    #pragma unroll
    for (int i = 0; i < 8; i++)
        #pragma unroll
        for (int j = 0; j < 4; j++) acc[i][j] = 0ull;

    for (int k0 = 0; k0 < K; k0 += 16) {
        #pragma unroll
        for (int p = 0; p < 8; p++) {
            int idx = p * 128 + tid;
            int m = idx >> 4, kk = idx & 15;
            As[kk][m] = W[(long)(m0 + m) * K + k0 + kk];
        }
        #pragma unroll
        for (int p = 0; p < 4; p++) {
            int idx = p * 128 + tid;
            int kk = idx >> 5, j4 = (idx & 31) * 4;
            int sp = sp0 + j4;
            float4 v = make_float4(0.f, 0.f, 0.f, 0.f);
            if (sp < Nsp) v = *(const float4*)&Xn[(long)(k0 + kk) * ldx + sp];
            *(float4*)&Bs[kk][j4] = v;
        }
        __syncthreads();
        #pragma unroll
        for (int kk = 0; kk < 16; kk++) {
            float4 b01 = *(const float4*)&Bs[kk][nt * 8];
            float4 b23 = *(const float4*)&Bs[kk][nt * 8 + 4];
            u64 bv[4];
            bv[0] = pack2(b01.x, b01.y); bv[1] = pack2(b01.z, b01.w);
            bv[2] = pack2(b23.x, b23.y); bv[3] = pack2(b23.z, b23.w);
            #pragma unroll
            for (int i = 0; i < 8; i++) {
                u64 av = splat2(As[kk][mt * 8 + i]);
                #pragma unroll
                for (int j = 0; j < 4; j++) fma2(acc[i][j], av, bv[j]);
            }
        }
        __syncthreads();
    }
    #pragma unroll
    for (int i = 0; i < 8; i++) {
        int m = m0 + mt * 8 + i;
        float bv = bias[m];
        #pragma unroll
        for (int j = 0; j < 4; j++) {
            int sp = sp0 + nt * 8 + 2 * j;
            if (sp < Nsp) {
                float2 r = unpack2(acc[i][j]);
                float2 o; o.x = r.x + bv; o.y = r.y + bv;
                *(float2*)&Yn[(long)m * Nsp + sp] = o;
            }
        }
    }
}

// ---------------- tf32 mma.sync score kernel ---------------------------------
// D_l[u][v] = sum_{c,t} Qp[ns][c][t][u] * Kp[ns][c][t+l][v]
// grid (ns=32, ksplit=4): 16 c per block. 10 warps: w -> (l=w/2, uhalf=w&1).
// Per k-tile of 32: Qs[96u][k:36stride], Ks[36k][v:57stride]; lag = +l row offset.
__global__ __launch_bounds__(320)
void score_mma(const float* __restrict__ Qp, const float* __restrict__ Kp,
               float* __restrict__ part)
{
    __shared__ u32 Qs[96 * 36];
    __shared__ u32 Ks[36 * 57];

    const int ns = blockIdx.x, ksb = blockIdx.y;
    const int tid = threadIdx.x, w = tid >> 5, lane = tid & 31;
    const int g = lane >> 2, tg = lane & 3;
    const int l = w >> 1, uh = w & 1;           // valid for w < 10
    const float* Qb = Qp + (long)ns * 1451520;
    const float* Kb = Kp + (long)ns * KP_PER_NS;

    float acc[3][7][4];
    #pragma unroll
    for (int i = 0; i < 3; i++)
        #pragma unroll
        for (int j = 0; j < 7; j++)
            #pragma unroll
            for (int e = 0; e < 4; e++) acc[i][j][e] = 0.f;

    for (int cc = 0; cc < 16; cc++) {
        const int c = ksb * 16 + cc;
        const float* Qc = Qb + (long)c * SPQ;
        const float* Kc = Kb + (long)c * SPK;
        for (int tt = 0; tt < 8; tt++) {
            const int t0 = tt * 32;
            const int kw = (tt == 7) ? 28 : 32;       // Q valid k-width (t < 252)
            const int krows = (tt == 7) ? 32 : 36;    // K rows available (t < 256)
            // stage Q tile: [u][k], zero-padded (u>=90 or k>=kw)
            for (int idx = tid; idx < 96 * 32; idx += 320) {
                int k = idx / 96, u = idx - (idx / 96) * 96;
                u32 val = 0;
                if (u < VQ_ && k < kw) val = tf32u(Qc[(long)(t0 + k) * VQ_ + u]);
                Qs[u * 36 + k] = val;
            }
            // stage K tile: [k][v], rows t0..t0+krows-1, zero-padded
            for (int idx = tid; idx < 36 * 56; idx += 320) {
                int k = idx / 56, v = idx - (idx / 56) * 56;
                u32 val = 0;
                if (v < VK_ && k < krows) val = tf32u(Kc[(long)(t0 + k) * VK_ + v]);
                Ks[k * 57 + v] = val;
            }
            __syncthreads();
            if (w < 10) {
                #pragma unroll
                for (int k8 = 0; k8 < 4; k8++) {
                    const int k0 = k8 * 8;
                    u32 a[3][4], b[7][2];
                    #pragma unroll
                    for (int i = 0; i < 3; i++) {
                        int u = uh * 48 + i * 16 + g;
                        a[i][0] = Qs[u * 36 + k0 + tg];
                        a[i][1] = Qs[(u + 8) * 36 + k0 + tg];
                        a[i][2] = Qs[u * 36 + k0 + tg + 4];
                        a[i][3] = Qs[(u + 8) * 36 + k0 + tg + 4];
                    }
                    #pragma unroll
                    for (int j = 0; j < 7; j++) {
                        b[j][0] = Ks[(k0 + tg + l) * 57 + j * 8 + g];
                        b[j][1] = Ks[(k0 + tg + 4 + l) * 57 + j * 8 + g];
                    }
                    #pragma unroll
                    for (int i = 0; i < 3; i++)
                        #pragma unroll
                        for (int j = 0; j < 7; j++) mma8(acc[i][j], a[i], b[j]);
                }
            }
            __syncthreads();
        }
    }
    if (w < 10) {
        float* pb = part + (((long)ksb * NS_ + ns) * 5 + l) * (VQ_ * VK_);
        #pragma unroll
        for (int i = 0; i < 3; i++) {
            #pragma unroll
            for (int j = 0; j < 7; j++) {
                int u = uh * 48 + i * 16 + g;
                int v = j * 8 + 2 * tg;
                if (v < VK_) {
                    if (u < VQ_) {
                        pb[u * VK_ + v]     = acc[i][j][0];
                        pb[u * VK_ + v + 1] = acc[i][j][1];
                    }
                    if (u + 8 < VQ_) {
                        pb[(u + 8) * VK_ + v]     = acc[i][j][2];
                        pb[(u + 8) * VK_ + v + 1] = acc[i][j][3];
                    }
                }
            }
        }
    }
}

// ---------------- combine lags + softmax over VK -----------------------------
__global__ __launch_bounds__(64)
void softmax_kernel(const float* __restrict__ part, float* __restrict__ att)
{
    const int row = blockIdx.x;
    const int ns = row / VQ_;
    const int u  = row - ns * VQ_;
    const int tid = threadIdx.x;
    const float inv_scale = rsqrtf((float)KTOT);

    __shared__ float red[64];
    float val = -1e30f;
    if (tid < VK_) {
        float mx = -1e30f, sm = 0.f;
        #pragma unroll
        for (int l = 0; l <= L_; l++) {
            float s = 0.f;
            #pragma unroll
            for (int ks = 0; ks < KSPLIT; ks++)
                s += part[((((long)ks * NS_ + ns) * 5 + l) * VQ_ + u) * VK_ + tid];
            mx = fmaxf(mx, s);
            sm += s;
        }
        val = 0.5f * (mx + sm * 0.2f) * inv_scale;
    }
    red[tid] = val; __syncthreads();
    for (int s = 32; s > 0; s >>= 1) {
        if (tid < s) red[tid] = fmaxf(red[tid], red[tid + s]);
        __syncthreads();
    }
    float rmax = red[0]; __syncthreads();
    float e = (tid < VK_) ? expf(val - rmax) : 0.f;
    red[tid] = e; __syncthreads();
    for (int s = 32; s > 0; s >>= 1) {
        if (tid < s) red[tid] += red[tid + s];
        __syncthreads();
    }
    float rsum = red[0];
    if (tid < VK_) att[(long)row * VK_ + tid] = e / rsum;
}

// ---------------- y = att @ V (unchanged) ------------------------------------
__global__ __launch_bounds__(256)
void ygemm_kernel(const float* __restrict__ Vp, const float* __restrict__ att,
                  float* __restrict__ y)
{
    const int ct0 = blockIdx.x * 128;
    const int ns  = blockIdx.z;
    const int n   = ns >> 2;
    const float* A = Vp + (long)n * VP_PER_N + (long)ct0 * VK_;
    const float* B = att + (long)ns * (VQ_ * VK_);
    float* Yb = y + (long)ns * Y_PER_NS + (long)ct0 * VQ_;

    __shared__ float As[50][132];
    __shared__ float Bs[50][96];

    const int tid = threadIdx.x;
    for (int idx = tid; idx < 128 * 50; idx += 256) {
        int r = idx / 50, k = idx - r * 50;
        As[k][r] = A[idx];
    }
    for (int idx = tid; idx < 96 * 50; idx += 256) {
        int u = idx / 50, k = idx - u * 50;
        Bs[k][u] = (u < VQ_) ? B[idx] : 0.f;
    }
    __syncthreads();

    const int mt = tid >> 4;
    const int nt = tid & 15;
    u64 acc[8][3];
    #pragma unroll
    for (int i = 0; i < 8; i++)
        #pragma unroll
        for (int j = 0; j < 3; j++) acc[i][j] = 0ull;

    #pragma unroll 10
    for (int k = 0; k < 50; k++) {
        u64 b[3];
        #pragma unroll
        for (int j = 0; j < 3; j++)
            b[j] = *(const u64*)&Bs[k][nt * 6 + 2 * j];
        #pragma unroll
        for (int i = 0; i < 8; i++) {
            u64 av = splat2(As[k][mt * 8 + i]);
            #pragma unroll
            for (int j = 0; j < 3; j++) fma2(acc[i][j], av, b[j]);
        }
    }
    #pragma unroll
    for (int i = 0; i < 8; i++) {
        int ct = mt * 8 + i;
        #pragma unroll
        for (int j = 0; j < 3; j++) {
            int vq = nt * 6 + 2 * j;
            if (vq < VQ_) {
                float2 r = unpack2(acc[i][j]);
                *(float2*)&Yb[(long)ct * VQ_ + vq] = r;
            }
        }
    }
}

// ---------------- batchnorm + epilogue (unchanged) ---------------------------
__global__ __launch_bounds__(256)
void bn_partial(const float* __restrict__ z, const float* __restrict__ d,
                float* __restrict__ partials)
{
    const int c = blockIdx.x, n = blockIdx.y, which = blockIdx.z;
    const float* src = (which ? d : z) + (long)(n * C_ + c) * SPO;
    float s1 = 0.f, s2 = 0.f;
    for (int i = threadIdx.x; i < SPO; i += 256) {
        float v = src[i];
        s1 += v; s2 += v * v;
    }
    __shared__ float r1[256], r2[256];
    int tid = threadIdx.x;
    r1[tid] = s1; r2[tid] = s2; __syncthreads();
    for (int s = 128; s > 0; s >>= 1) {
        if (tid < s) { r1[tid] += r1[tid + s]; r2[tid] += r2[tid + s]; }
        __syncthreads();
    }
    if (tid == 0) {
        partials[((which * C_ + c) * N_ + n) * 2 + 0] = r1[0];
        partials[((which * C_ + c) * N_ + n) * 2 + 1] = r2[0];
    }
}

__global__ __launch_bounds__(128)
void bn_final(const float* __restrict__ partials,
              const float* __restrict__ gz, const float* __restrict__ bz,
              const float* __restrict__ gd, const float* __restrict__ bd,
              float* __restrict__ coef)
{
    int tid = threadIdx.x;
    if (tid >= 128) return;
    int which = tid >> 6, c = tid & 63;
    float s1 = 0.f, s2 = 0.f;
    for (int n = 0; n < N_; n++) {
        s1 += partials[((which * C_ + c) * N_ + n) * 2 + 0];
        s2 += partials[((which * C_ + c) * N_ + n) * 2 + 1];
    }
    float inv = 1.0f / (float)BN_COUNT;
    float mean = s1 * inv;
    float var  = s2 * inv - mean * mean;
    float rstd = rsqrtf(var + 1e-5f);
    float g = which ? gd[c] : gz[c];
    float b = which ? bd[c] : bz[c];
    float a = g * rstd;
    coef[tid * 2 + 0] = a;
    coef[tid * 2 + 1] = b - mean * a;
}

__global__ __launch_bounds__(256)
void final_kernel(const float* __restrict__ z, const float* __restrict__ d,
                  const float* __restrict__ coef, float* __restrict__ out)
{
    long i = (long)blockIdx.x * 256 + threadIdx.x;
    if (i >= OUT_TOTAL) return;
    int c = (int)((i / SPO) & (C_ - 1));
    float az = coef[c * 2], bz_ = coef[c * 2 + 1];
    float ad = coef[(C_ + c) * 2], bd_ = coef[(C_ + c) * 2 + 1];
    float v = fmaf(az, z[i], bz_) + fmaf(ad, d[i], bd_);
    out[i] = v > 0.f ? v : 0.1f * v;
}

// ---------------- launch -----------------------------------------------------
extern "C" void kernel_launch(void* const* d_in, const int* in_sizes, int n_in,
                              void* d_out, int out_size)
{
    const float* x_q   = (const float*)d_in[0];
    const float* x_k   = (const float*)d_in[1];
    const float* x_v   = (const float*)d_in[2];
    const float* Wq    = (const float*)d_in[3];
    const float* bq    = (const float*)d_in[4];
    const float* Wk    = (const float*)d_in[5];
    const float* bk    = (const float*)d_in[6];
    const float* Wv    = (const float*)d_in[7];
    const float* bv    = (const float*)d_in[8];
    const float* Wout  = (const float*)d_in[9];
    const float* bout  = (const float*)d_in[10];
    const float* gout  = (const float*)d_in[11];
    const float* bnout = (const float*)d_in[12];
    const float* Wdown = (const float*)d_in[13];
    const float* bdown = (const float*)d_in[14];
    const float* gdown = (const float*)d_in[15];
    const float* bndwn = (const float*)d_in[16];

    float *Qp, *Kp, *Vp, *part, *att, *y, *z, *dd, *bnp, *coef;
    cudaGetSymbolAddress((void**)&Qp,   g_Qp);
    cudaGetSymbolAddress((void**)&Kp,   g_Kp);
    cudaGetSymbolAddress((void**)&Vp,   g_Vp);
    cudaGetSymbolAddress((void**)&part, g_part);
    cudaGetSymbolAddress((void**)&att,  g_att);
    cudaGetSymbolAddress((void**)&y,    g_y);
    cudaGetSymbolAddress((void**)&z,    g_z);
    cudaGetSymbolAddress((void**)&dd,   g_d);
    cudaGetSymbolAddress((void**)&bnp,  g_bnpart);
    cudaGetSymbolAddress((void**)&coef, g_bncoef);

    // projections
    conv_gemm<<<dim3((SPQ + 127) / 128, 4, N_), 128>>>(Wq, bq, x_q, Qp, 256, 64, SPQ, SPO, 1474560L, 5806080L);
    conv_gemm<<<dim3((SPK + 127) / 128, 4, N_), 128>>>(Wk, bk, x_k, Kp, 256, 64, SPK, SPK, 819200L, 3276800L);
    conv_gemm<<<dim3((SPK + 127) / 128, 1, N_), 128>>>(Wv, bv, x_v, Vp, 64, 64, SPK, SPK, 819200L, 819200L);
    conv_gemm<<<dim3((SPO + 127) / 128, 1, N_), 128>>>(Wdown, bdown, x_q, dd, 64, 64, SPO, SPO, 1474560L, 1474560L);

    // tensor-core (mma.sync tf32) multi-lag scores + softmax
    score_mma<<<dim3(NS_, KSPLIT), 320>>>(Qp, Kp, part);
    softmax_kernel<<<NS_ * VQ_, 64>>>(part, att);

    // y = att @ V, out projection
    ygemm_kernel<<<dim3(128, 1, NS_), 256>>>(Vp, att, y);
    conv_gemm<<<dim3((SPO + 127) / 128, 1, N_), 128>>>(Wout, bout, y, z, 64, 256, SPO, SPO, 5898240L, 1474560L);

    // batchnorm + fused epilogue
    bn_partial<<<dim3(C_, N_, 2), 256>>>(z, dd, bnp);
    bn_final<<<1, 128>>>(bnp, gout, bnout, gdown, bndwn, coef);
    final_kernel<<<(OUT_TOTAL + 255) / 256, 256>>>(z, dd, coef, (float*)d_out);
}

// round 10
// speedup vs baseline: 1.3538x; 1.0589x over previous
#include <cuda_runtime.h>
#include <cuda_bf16.h>
#include <math.h>

#define N_   8
#define C_   64
#define T_   256
#define VQ_  90
#define VK_  50
#define S_   4
#define L_   4
#define Tq_  252
#define SC_  256
#define NS_  32
#define KSPLIT 4
#define KTOT 16128

#define KP_PER_NS  819200
#define VP_PER_N   819200
#define Y_PER_NS   1474560
#define SPQ  22680
#define SPK  12800
#define SPO  23040
#define OUT_TOTAL 11796480
#define BN_COUNT  184320

typedef unsigned long long u64;
typedef unsigned int u32;

// ---- tf32 mma.sync helpers (base PTX, validated in R9) ----------------------
__device__ __forceinline__ u32 tf32u(float x) {
    u32 r; asm("cvt.rna.tf32.f32 %0, %1;" : "=r"(r) : "f"(x)); return r;
}
__device__ __forceinline__ void mma8(float* c, const u32* a, const u32* b) {
    asm volatile("mma.sync.aligned.m16n8k8.row.col.f32.tf32.tf32.f32 "
        "{%0,%1,%2,%3}, {%4,%5,%6,%7}, {%8,%9}, {%0,%1,%2,%3};"
        : "+f"(c[0]), "+f"(c[1]), "+f"(c[2]), "+f"(c[3])
        : "r"(a[0]), "r"(a[1]), "r"(a[2]), "r"(a[3]), "r"(b[0]), "r"(b[1]));
}

// ---------------- scratch ----------------------------------------------------
__device__ float g_Qp[(long)N_*SC_*Tq_*VQ_];
__device__ float g_Kp[(long)N_*SC_*T_*VK_];
__device__ float g_Vp[(long)N_*C_*T_*VK_];
__device__ float g_part[(long)KSPLIT*NS_*(L_+1)*VQ_*VK_];
__device__ float g_att[(long)NS_*VQ_*VK_];
__device__ float g_y[(long)N_*SC_*T_*VQ_];
__device__ float g_z[(long)OUT_TOTAL];
__device__ float g_d[(long)OUT_TOTAL];
__device__ float g_bnpart[2*C_*N_*2];
__device__ float g_bncoef[2*C_*2];

// ---------------- conv1x1 via mma.sync tf32 ----------------------------------
// Y[n][m][sp] = sum_k W[m][k] X[n][k][sp] + b[m]
// block 64m x 256n, BK=16, 256 thr (8 warps: 2 m-warps x 4 n-warps)
// smem strides == 8 (mod 32) -> fragment LDS conflict-free (bank = 8*tg+g)
__global__ __launch_bounds__(256)
void conv_mma(const float* __restrict__ W, const float* __restrict__ bias,
              const float* __restrict__ X, float* __restrict__ Y,
              int M, int K, int Nsp, int ldx, long xbatch, long ybatch)
{
    __shared__ u32 Ws[16 * 72];    // [k][m]
    __shared__ u32 Xs[16 * 264];   // [k][n]

    const int n  = blockIdx.z;
    const int m0 = blockIdx.y * 64;
    const int n0 = blockIdx.x * 256;
    const float* Xn = X + (long)n * xbatch;
    float* Yn = Y + (long)n * ybatch;

    const int tid = threadIdx.x, w = tid >> 5, lane = tid & 31;
    const int g = lane >> 2, tg = lane & 3;
    const int mw = (w & 1) * 32, nw = (w >> 1) * 64;

    float acc[2][8][4];
    #pragma unroll
    for (int i = 0; i < 2; i++)
        #pragma unroll
        for (int j = 0; j < 8; j++)
            #pragma unroll
            for (int e = 0; e < 4; e++) acc[i][j][e] = 0.f;

    for (int k0 = 0; k0 < K; k0 += 16) {
        // stage W tile [16k][64m], k-major
        #pragma unroll
        for (int p = 0; p < 4; p++) {
            int i = p * 256 + tid;
            int m = i & 63, kk = i >> 6;
            Ws[kk * 72 + m] = tf32u(W[(long)(m0 + m) * K + k0 + kk]);
        }
        // stage X tile [16k][256n] with float4 loads
        #pragma unroll
        for (int p = 0; p < 4; p++) {
            int i = p * 256 + tid;
            int kk = i >> 6, j4 = (i & 63) * 4;
            int col = n0 + j4;
            const float* src = &Xn[(long)(k0 + kk) * ldx + col];
            u32* dst = &Xs[kk * 264 + j4];
            if (col + 4 <= Nsp) {
                float4 v = *(const float4*)src;
                dst[0] = tf32u(v.x); dst[1] = tf32u(v.y);
                dst[2] = tf32u(v.z); dst[3] = tf32u(v.w);
            } else {
                #pragma unroll
                for (int e = 0; e < 4; e++)
                    dst[e] = (col + e < Nsp) ? tf32u(src[e]) : 0u;
            }
        }
        __syncthreads();
        #pragma unroll
        for (int k8 = 0; k8 < 16; k8 += 8) {
            u32 a[2][4];
            #pragma unroll
            for (int mi = 0; mi < 2; mi++) {
                int m = mw + mi * 16;
                a[mi][0] = Ws[(k8 + tg) * 72 + m + g];
                a[mi][1] = Ws[(k8 + tg) * 72 + m + g + 8];
                a[mi][2] = Ws[(k8 + tg + 4) * 72 + m + g];
                a[mi][3] = Ws[(k8 + tg + 4) * 72 + m + g + 8];
            }
            #pragma unroll
            for (int ji = 0; ji < 8; ji++) {
                u32 b[2];
                b[0] = Xs[(k8 + tg) * 264 + nw + ji * 8 + g];
                b[1] = Xs[(k8 + tg + 4) * 264 + nw + ji * 8 + g];
                mma8(acc[0][ji], a[0], b);
                mma8(acc[1][ji], a[1], b);
            }
        }
        __syncthreads();
    }
    #pragma unroll
    for (int mi = 0; mi < 2; mi++) {
        int mrow = m0 + mw + mi * 16 + g;
        float bv0 = bias[mrow], bv1 = bias[mrow + 8];
        #pragma unroll
        for (int ji = 0; ji < 8; ji++) {
            int col = n0 + nw + ji * 8 + 2 * tg;
            if (col < Nsp) {     // Nsp even, col even -> col+1 < Nsp too
                float2 o0; o0.x = acc[mi][ji][0] + bv0; o0.y = acc[mi][ji][1] + bv0;
                float2 o1; o1.x = acc[mi][ji][2] + bv1; o1.y = acc[mi][ji][3] + bv1;
                *(float2*)&Yn[(long)mrow * Nsp + col] = o0;
                *(float2*)&Yn[(long)(mrow + 8) * Nsp + col] = o1;
            }
        }
    }
}

// ---------------- tf32 mma.sync score kernel (unchanged, R9-validated) -------
__global__ __launch_bounds__(320)
void score_mma(const float* __restrict__ Qp, const float* __restrict__ Kp,
               float* __restrict__ part)
{
    __shared__ u32 Qs[96 * 36];
    __shared__ u32 Ks[36 * 57];

    const int ns = blockIdx.x, ksb = blockIdx.y;
    const int tid = threadIdx.x, w = tid >> 5, lane = tid & 31;
    const int g = lane >> 2, tg = lane & 3;
    const int l = w >> 1, uh = w & 1;
    const float* Qb = Qp + (long)ns * 1451520;
    const float* Kb = Kp + (long)ns * KP_PER_NS;

    float acc[3][7][4];
    #pragma unroll
    for (int i = 0; i < 3; i++)
        #pragma unroll
        for (int j = 0; j < 7; j++)
            #pragma unroll
            for (int e = 0; e < 4; e++) acc[i][j][e] = 0.f;

    for (int cc = 0; cc < 16; cc++) {
        const int c = ksb * 16 + cc;
        const float* Qc = Qb + (long)c * SPQ;
        const float* Kc = Kb + (long)c * SPK;
        for (int tt = 0; tt < 8; tt++) {
            const int t0 = tt * 32;
            const int kw = (tt == 7) ? 28 : 32;
            const int krows = (tt == 7) ? 32 : 36;
            for (int idx = tid; idx < 96 * 32; idx += 320) {
                int k = idx / 96, u = idx - (idx / 96) * 96;
                u32 val = 0;
                if (u < VQ_ && k < kw) val = tf32u(Qc[(long)(t0 + k) * VQ_ + u]);
                Qs[u * 36 + k] = val;
            }
            for (int idx = tid; idx < 36 * 56; idx += 320) {
                int k = idx / 56, v = idx - (idx / 56) * 56;
                u32 val = 0;
                if (v < VK_ && k < krows) val = tf32u(Kc[(long)(t0 + k) * VK_ + v]);
                Ks[k * 57 + v] = val;
            }
            __syncthreads();
            if (w < 10) {
                #pragma unroll
                for (int k8 = 0; k8 < 4; k8++) {
                    const int k0 = k8 * 8;
                    u32 a[3][4], b[7][2];
                    #pragma unroll
                    for (int i = 0; i < 3; i++) {
                        int u = uh * 48 + i * 16 + g;
                        a[i][0] = Qs[u * 36 + k0 + tg];
                        a[i][1] = Qs[(u + 8) * 36 + k0 + tg];
                        a[i][2] = Qs[u * 36 + k0 + tg + 4];
                        a[i][3] = Qs[(u + 8) * 36 + k0 + tg + 4];
                    }
                    #pragma unroll
                    for (int j = 0; j < 7; j++) {
                        b[j][0] = Ks[(k0 + tg + l) * 57 + j * 8 + g];
                        b[j][1] = Ks[(k0 + tg + 4 + l) * 57 + j * 8 + g];
                    }
                    #pragma unroll
                    for (int i = 0; i < 3; i++)
                        #pragma unroll
                        for (int j = 0; j < 7; j++) mma8(acc[i][j], a[i], b[j]);
                }
            }
            __syncthreads();
        }
    }
    if (w < 10) {
        float* pb = part + (((long)ksb * NS_ + ns) * 5 + l) * (VQ_ * VK_);
        #pragma unroll
        for (int i = 0; i < 3; i++) {
            #pragma unroll
            for (int j = 0; j < 7; j++) {
                int u = uh * 48 + i * 16 + g;
                int v = j * 8 + 2 * tg;
                if (v < VK_) {
                    if (u < VQ_) {
                        pb[u * VK_ + v]     = acc[i][j][0];
                        pb[u * VK_ + v + 1] = acc[i][j][1];
                    }
                    if (u + 8 < VQ_) {
                        pb[(u + 8) * VK_ + v]     = acc[i][j][2];
                        pb[(u + 8) * VK_ + v + 1] = acc[i][j][3];
                    }
                }
            }
        }
    }
}

// ---------------- combine lags + softmax over VK (unchanged) -----------------
__global__ __launch_bounds__(64)
void softmax_kernel(const float* __restrict__ part, float* __restrict__ att)
{
    const int row = blockIdx.x;
    const int ns = row / VQ_;
    const int u  = row - ns * VQ_;
    const int tid = threadIdx.x;
    const float inv_scale = rsqrtf((float)KTOT);

    __shared__ float red[64];
    float val = -1e30f;
    if (tid < VK_) {
        float mx = -1e30f, sm = 0.f;
        #pragma unroll
        for (int l = 0; l <= L_; l++) {
            float s = 0.f;
            #pragma unroll
            for (int ks = 0; ks < KSPLIT; ks++)
                s += part[((((long)ks * NS_ + ns) * 5 + l) * VQ_ + u) * VK_ + tid];
            mx = fmaxf(mx, s);
            sm += s;
        }
        val = 0.5f * (mx + sm * 0.2f) * inv_scale;
    }
    red[tid] = val; __syncthreads();
    for (int s = 32; s > 0; s >>= 1) {
        if (tid < s) red[tid] = fmaxf(red[tid], red[tid + s]);
        __syncthreads();
    }
    float rmax = red[0]; __syncthreads();
    float e = (tid < VK_) ? expf(val - rmax) : 0.f;
    red[tid] = e; __syncthreads();
    for (int s = 32; s > 0; s >>= 1) {
        if (tid < s) red[tid] += red[tid + s];
        __syncthreads();
    }
    float rsum = red[0];
    if (tid < VK_) att[(long)row * VK_ + tid] = e / rsum;
}

// ---------------- y = att @ V via mma.sync tf32 ------------------------------
// Y[ns][ct][vq] = sum_vk V[n][ct][vk] * att[ns][vq][vk]
// block 128ct x 96vq, K=50 pad 56, 256 thr (4 m-warps x 2 n-warps)
// dynamic smem: Vs[56][136] + Bs[56][104] (strides == 8 mod 32, conflict-free)
#define YG_SMEM ((56*136 + 56*104) * 4)
__global__ __launch_bounds__(256)
void ygemm_mma(const float* __restrict__ Vp, const float* __restrict__ att,
               float* __restrict__ y)
{
    extern __shared__ u32 dynsh[];
    u32* Vs = dynsh;            // [k][ct] stride 136
    u32* Bs = dynsh + 56 * 136; // [k][vq] stride 104

    const int ct0 = blockIdx.x * 128;
    const int ns  = blockIdx.y;
    const int n   = ns >> 2;
    const float* A = Vp + (long)n * VP_PER_N + (long)ct0 * VK_;
    const float* B = att + (long)ns * (VQ_ * VK_);
    float* Yb = y + (long)ns * Y_PER_NS;

    const int tid = threadIdx.x, w = tid >> 5, lane = tid & 31;
    const int g = lane >> 2, tg = lane & 3;
    const int mw = (w & 3) * 32, nw = (w >> 2) * 48;

    // stage V transpose -> [k][ct]
    for (int idx = tid; idx < 128 * 56; idx += 256) {
        int ct = idx / 56, k = idx - (idx / 56) * 56;
        Vs[k * 136 + ct] = (k < VK_) ? tf32u(A[ct * VK_ + k]) : 0u;
    }
    // stage att transpose -> [k][vq]
    for (int idx = tid; idx < 96 * 56; idx += 256) {
        int vq = idx / 56, k = idx - (idx / 56) * 56;
        Bs[k * 104 + vq] = (k < VK_ && vq < VQ_) ? tf32u(B[vq * VK_ + k]) : 0u;
    }
    __syncthreads();

    float acc[2][6][4];
    #pragma unroll
    for (int i = 0; i < 2; i++)
        #pragma unroll
        for (int j = 0; j < 6; j++)
            #pragma unroll
            for (int e = 0; e < 4; e++) acc[i][j][e] = 0.f;

    #pragma unroll
    for (int kq = 0; kq < 7; kq++) {
        const int k0 = kq * 8;
        u32 a[2][4];
        #pragma unroll
        for (int mi = 0; mi < 2; mi++) {
            int m = mw + mi * 16;
            a[mi][0] = Vs[(k0 + tg) * 136 + m + g];
            a[mi][1] = Vs[(k0 + tg) * 136 + m + g + 8];
            a[mi][2] = Vs[(k0 + tg + 4) * 136 + m + g];
            a[mi][3] = Vs[(k0 + tg + 4) * 136 + m + g + 8];
        }
        #pragma unroll
        for (int ji = 0; ji < 6; ji++) {
            u32 b[2];
            b[0] = Bs[(k0 + tg) * 104 + nw + ji * 8 + g];
            b[1] = Bs[(k0 + tg + 4) * 104 + nw + ji * 8 + g];
            mma8(acc[0][ji], a[0], b);
            mma8(acc[1][ji], a[1], b);
        }
    }
    #pragma unroll
    for (int mi = 0; mi < 2; mi++) {
        int ct = ct0 + mw + mi * 16 + g;
        #pragma unroll
        for (int ji = 0; ji < 6; ji++) {
            int vq = nw + ji * 8 + 2 * tg;
            if (vq < VQ_) {    // vq even, <=88 -> vq+1 valid
                float2 o0; o0.x = acc[mi][ji][0]; o0.y = acc[mi][ji][1];
                float2 o1; o1.x = acc[mi][ji][2]; o1.y = acc[mi][ji][3];
                *(float2*)&Yb[(long)ct * VQ_ + vq] = o0;
                *(float2*)&Yb[(long)(ct + 8) * VQ_ + vq] = o1;
            }
        }
    }
}

// ---------------- batchnorm + epilogue (unchanged) ---------------------------
__global__ __launch_bounds__(256)
void bn_partial(const float* __restrict__ z, const float* __restrict__ d,
                float* __restrict__ partials)
{
    const int c = blockIdx.x, n = blockIdx.y, which = blockIdx.z;
    const float* src = (which ? d : z) + (long)(n * C_ + c) * SPO;
    float s1 = 0.f, s2 = 0.f;
    for (int i = threadIdx.x; i < SPO; i += 256) {
        float v = src[i];
        s1 += v; s2 += v * v;
    }
    __shared__ float r1[256], r2[256];
    int tid = threadIdx.x;
    r1[tid] = s1; r2[tid] = s2; __syncthreads();
    for (int s = 128; s > 0; s >>= 1) {
        if (tid < s) { r1[tid] += r1[tid + s]; r2[tid] += r2[tid + s]; }
        __syncthreads();
    }
    if (tid == 0) {
        partials[((which * C_ + c) * N_ + n) * 2 + 0] = r1[0];
        partials[((which * C_ + c) * N_ + n) * 2 + 1] = r2[0];
    }
}

__global__ __launch_bounds__(128)
void bn_final(const float* __restrict__ partials,
              const float* __restrict__ gz, const float* __restrict__ bz,
              const float* __restrict__ gd, const float* __restrict__ bd,
              float* __restrict__ coef)
{
    int tid = threadIdx.x;
    if (tid >= 128) return;
    int which = tid >> 6, c = tid & 63;
    float s1 = 0.f, s2 = 0.f;
    for (int n = 0; n < N_; n++) {
        s1 += partials[((which * C_ + c) * N_ + n) * 2 + 0];
        s2 += partials[((which * C_ + c) * N_ + n) * 2 + 1];
    }
    float inv = 1.0f / (float)BN_COUNT;
    float mean = s1 * inv;
    float var  = s2 * inv - mean * mean;
    float rstd = rsqrtf(var + 1e-5f);
    float g = which ? gd[c] : gz[c];
    float b = which ? bd[c] : bz[c];
    float a = g * rstd;
    coef[tid * 2 + 0] = a;
    coef[tid * 2 + 1] = b - mean * a;
}

__global__ __launch_bounds__(256)
void final_kernel(const float* __restrict__ z, const float* __restrict__ d,
                  const float* __restrict__ coef, float* __restrict__ out)
{
    long i = (long)blockIdx.x * 256 + threadIdx.x;
    if (i >= OUT_TOTAL) return;
    int c = (int)((i / SPO) & (C_ - 1));
    float az = coef[c * 2], bz_ = coef[c * 2 + 1];
    float ad = coef[(C_ + c) * 2], bd_ = coef[(C_ + c) * 2 + 1];
    float v = fmaf(az, z[i], bz_) + fmaf(ad, d[i], bd_);
    out[i] = v > 0.f ? v : 0.1f * v;
}

// ---------------- launch -----------------------------------------------------
extern "C" void kernel_launch(void* const* d_in, const int* in_sizes, int n_in,
                              void* d_out, int out_size)
{
    const float* x_q   = (const float*)d_in[0];
    const float* x_k   = (const float*)d_in[1];
    const float* x_v   = (const float*)d_in[2];
    const float* Wq    = (const float*)d_in[3];
    const float* bq    = (const float*)d_in[4];
    const float* Wk    = (const float*)d_in[5];
    const float* bk    = (const float*)d_in[6];
    const float* Wv    = (const float*)d_in[7];
    const float* bv    = (const float*)d_in[8];
    const float* Wout  = (const float*)d_in[9];
    const float* bout  = (const float*)d_in[10];
    const float* gout  = (const float*)d_in[11];
    const float* bnout = (const float*)d_in[12];
    const float* Wdown = (const float*)d_in[13];
    const float* bdown = (const float*)d_in[14];
    const float* gdown = (const float*)d_in[15];
    const float* bndwn = (const float*)d_in[16];

    float *Qp, *Kp, *Vp, *part, *att, *y, *z, *dd, *bnp, *coef;
    cudaGetSymbolAddress((void**)&Qp,   g_Qp);
    cudaGetSymbolAddress((void**)&Kp,   g_Kp);
    cudaGetSymbolAddress((void**)&Vp,   g_Vp);
    cudaGetSymbolAddress((void**)&part, g_part);
    cudaGetSymbolAddress((void**)&att,  g_att);
    cudaGetSymbolAddress((void**)&y,    g_y);
    cudaGetSymbolAddress((void**)&z,    g_z);
    cudaGetSymbolAddress((void**)&dd,   g_d);
    cudaGetSymbolAddress((void**)&bnp,  g_bnpart);
    cudaGetSymbolAddress((void**)&coef, g_bncoef);

    cudaFuncSetAttribute(ygemm_mma, cudaFuncAttributeMaxDynamicSharedMemorySize, YG_SMEM);

    // projections (all tensor-core now)
    conv_mma<<<dim3(89, 4, N_), 256>>>(Wq, bq, x_q, Qp, 256, 64, SPQ, SPO, 1474560L, 5806080L);
    conv_mma<<<dim3(50, 4, N_), 256>>>(Wk, bk, x_k, Kp, 256, 64, SPK, SPK, 819200L, 3276800L);
    conv_mma<<<dim3(50, 1, N_), 256>>>(Wv, bv, x_v, Vp, 64, 64, SPK, SPK, 819200L, 819200L);
    conv_mma<<<dim3(90, 1, N_), 256>>>(Wdown, bdown, x_q, dd, 64, 64, SPO, SPO, 1474560L, 1474560L);

    // tensor-core multi-lag scores + softmax
    score_mma<<<dim3(NS_, KSPLIT), 320>>>(Qp, Kp, part);
    softmax_kernel<<<NS_ * VQ_, 64>>>(part, att);

    // y = att @ V (tensor-core), out projection (tensor-core)
    ygemm_mma<<<dim3(128, NS_), 256, YG_SMEM>>>(Vp, att, y);
    conv_mma<<<dim3(90, 1, N_), 256>>>(Wout, bout, y, z, 64, 256, SPO, SPO, 5898240L, 1474560L);

    // batchnorm + fused epilogue
    bn_partial<<<dim3(C_, N_, 2), 256>>>(z, dd, bnp);
    bn_final<<<1, 128>>>(bnp, gout, bnout, gdown, bndwn, coef);
    final_kernel<<<(OUT_TOTAL + 255) / 256, 256>>>(z, dd, coef, (float*)d_out);
}

// round 11
// speedup vs baseline: 1.7074x; 1.2612x over previous
#include <cuda_runtime.h>
#include <cuda_bf16.h>
#include <math.h>

#define N_   8
#define C_   64
#define T_   256
#define VQ_  90
#define VK_  50
#define S_   4
#define L_   4
#define Tq_  252
#define SC_  256
#define NS_  32
#define KSPLIT 8
#define CPB   8            // c per score block = 64/KSPLIT
#define KTOT 16128

#define KP_PER_NS  819200
#define VP_PER_N   819200
#define Y_PER_NS   1474560
#define SPQ  22680
#define SPK  12800
#define SPO  23040
#define OUT_TOTAL 11796480
#define BN_COUNT  184320

typedef unsigned long long u64;
typedef unsigned int u32;

// ---- tf32 mma.sync helpers (base PTX, validated R9/R10) ---------------------
__device__ __forceinline__ u32 tf32u(float x) {
    u32 r; asm("cvt.rna.tf32.f32 %0, %1;" : "=r"(r) : "f"(x)); return r;
}
__device__ __forceinline__ void mma8(float* c, const u32* a, const u32* b) {
    asm volatile("mma.sync.aligned.m16n8k8.row.col.f32.tf32.tf32.f32 "
        "{%0,%1,%2,%3}, {%4,%5,%6,%7}, {%8,%9}, {%0,%1,%2,%3};"
        : "+f"(c[0]), "+f"(c[1]), "+f"(c[2]), "+f"(c[3])
        : "r"(a[0]), "r"(a[1]), "r"(a[2]), "r"(a[3]), "r"(b[0]), "r"(b[1]));
}

// ---------------- scratch ----------------------------------------------------
__device__ float g_Qp[(long)N_*SC_*Tq_*VQ_];
__device__ float g_Kp[(long)N_*SC_*T_*VK_];
__device__ float g_Vp[(long)N_*C_*T_*VK_];
__device__ float g_part[(long)KSPLIT*NS_*(L_+1)*VQ_*VK_];
__device__ float g_att[(long)NS_*VQ_*VK_];
__device__ float g_y[(long)N_*SC_*T_*VQ_];
__device__ float g_z[(long)OUT_TOTAL];
__device__ float g_d[(long)OUT_TOTAL];
__device__ float g_bnpart[2*C_*N_*2];
__device__ float g_bncoef[2*C_*2];

// ---------------- conv1x1 via mma.sync tf32, double-buffered -----------------
// Y[n][m][sp] = sum_k W[m][k] X[n][k][sp] + b[m]
// block 64m x 256n, BK=16, 256 thr (2 m-warps x 4 n-warps), 2-stage pipeline
__global__ __launch_bounds__(256)
void conv_mma(const float* __restrict__ W, const float* __restrict__ bias,
              const float* __restrict__ X, float* __restrict__ Y,
              int M, int K, int Nsp, int ldx, long xbatch, long ybatch)
{
    __shared__ u32 Ws[2][16 * 72];    // [k][m]
    __shared__ u32 Xs[2][16 * 264];   // [k][n]

    const int n  = blockIdx.z;
    const int m0 = blockIdx.y * 64;
    const int n0 = blockIdx.x * 256;
    const float* Xn = X + (long)n * xbatch;
    float* Yn = Y + (long)n * ybatch;

    const int tid = threadIdx.x, w = tid >> 5, lane = tid & 31;
    const int g = lane >> 2, tg = lane & 3;
    const int mw = (w & 1) * 32, nw = (w >> 1) * 64;
    const int KT = K >> 4;

    float wr[4];
    float4 xr[4];

    auto loadregs = [&](int kt) {
        const int k0 = kt * 16;
        #pragma unroll
        for (int p = 0; p < 4; p++) {
            int i = p * 256 + tid;
            int m = i & 63, kk = i >> 6;
            wr[p] = W[(long)(m0 + m) * K + k0 + kk];
        }
        #pragma unroll
        for (int p = 0; p < 4; p++) {
            int i = p * 256 + tid;
            int kk = i >> 6, j4 = (i & 63) * 4;
            int col = n0 + j4;
            const float* src = &Xn[(long)(k0 + kk) * ldx + col];
            if (col + 4 <= Nsp) {
                xr[p] = *(const float4*)src;
            } else {
                xr[p].x = (col     < Nsp) ? src[0] : 0.f;
                xr[p].y = (col + 1 < Nsp) ? src[1] : 0.f;
                xr[p].z = (col + 2 < Nsp) ? src[2] : 0.f;
                xr[p].w = (col + 3 < Nsp) ? src[3] : 0.f;
            }
        }
    };
    auto storeregs = [&](int buf) {
        #pragma unroll
        for (int p = 0; p < 4; p++) {
            int i = p * 256 + tid;
            Ws[buf][(i >> 6) * 72 + (i & 63)] = tf32u(wr[p]);
        }
        #pragma unroll
        for (int p = 0; p < 4; p++) {
            int i = p * 256 + tid;
            int kk = i >> 6, j4 = (i & 63) * 4;
            uint4 v;
            v.x = tf32u(xr[p].x); v.y = tf32u(xr[p].y);
            v.z = tf32u(xr[p].z); v.w = tf32u(xr[p].w);
            *(uint4*)&Xs[buf][kk * 264 + j4] = v;   // STS.128, conflict-free
        }
    };

    float acc[2][8][4];
    #pragma unroll
    for (int i = 0; i < 2; i++)
        #pragma unroll
        for (int j = 0; j < 8; j++)
            #pragma unroll
            for (int e = 0; e < 4; e++) acc[i][j][e] = 0.f;

    loadregs(0);
    storeregs(0);
    __syncthreads();

    for (int kt = 0; kt < KT; kt++) {
        const int buf = kt & 1;
        if (kt + 1 < KT) loadregs(kt + 1);
        const u32* Wb = Ws[buf];
        const u32* Xb = Xs[buf];
        #pragma unroll
        for (int k8 = 0; k8 < 16; k8 += 8) {
            u32 a[2][4];
            #pragma unroll
            for (int mi = 0; mi < 2; mi++) {
                int m = mw + mi * 16;
                a[mi][0] = Wb[(k8 + tg) * 72 + m + g];
                a[mi][1] = Wb[(k8 + tg) * 72 + m + g + 8];
                a[mi][2] = Wb[(k8 + tg + 4) * 72 + m + g];
                a[mi][3] = Wb[(k8 + tg + 4) * 72 + m + g + 8];
            }
            #pragma unroll
            for (int ji = 0; ji < 8; ji++) {
                u32 b[2];
                b[0] = Xb[(k8 + tg) * 264 + nw + ji * 8 + g];
                b[1] = Xb[(k8 + tg + 4) * 264 + nw + ji * 8 + g];
                mma8(acc[0][ji], a[0], b);
                mma8(acc[1][ji], a[1], b);
            }
        }
        if (kt + 1 < KT) storeregs(buf ^ 1);
        __syncthreads();
    }

    #pragma unroll
    for (int mi = 0; mi < 2; mi++) {
        int mrow = m0 + mw + mi * 16 + g;
        float bv0 = bias[mrow], bv1 = bias[mrow + 8];
        #pragma unroll
        for (int ji = 0; ji < 8; ji++) {
            int col = n0 + nw + ji * 8 + 2 * tg;
            if (col < Nsp) {
                float2 o0; o0.x = acc[mi][ji][0] + bv0; o0.y = acc[mi][ji][1] + bv0;
                float2 o1; o1.x = acc[mi][ji][2] + bv1; o1.y = acc[mi][ji][3] + bv1;
                *(float2*)&Yn[(long)mrow * Nsp + col] = o0;
                *(float2*)&Yn[(long)(mrow + 8) * Nsp + col] = o1;
            }
        }
    }
}

// ---------------- tf32 mma.sync score kernel, double-buffered ----------------
// D_l[u][v] = sum_{c,t} Qp[ns][c][t][u] * Kp[ns][c][t+l][v]
// grid (ns=32, ksplit=8): 8 c per block, 64 k-tiles of 32, 2-stage pipeline.
__global__ __launch_bounds__(320)
void score_mma(const float* __restrict__ Qp, const float* __restrict__ Kp,
               float* __restrict__ part)
{
    __shared__ u32 Qs[2][96 * 36];
    __shared__ u32 Ks[2][36 * 57];

    const int ns = blockIdx.x, ksb = blockIdx.y;
    const int tid = threadIdx.x, w = tid >> 5, lane = tid & 31;
    const int g = lane >> 2, tg = lane & 3;
    const int l = w >> 1, uh = w & 1;
    const float* Qb = Qp + (long)ns * 1451520;
    const float* Kb = Kp + (long)ns * KP_PER_NS;

    u32 qr[10], kr[7];

    auto loadregs = [&](int it) {
        const int c = ksb * CPB + (it >> 3), tt = it & 7;
        const float* Qc = Qb + (long)c * SPQ;
        const float* Kc = Kb + (long)c * SPK;
        const int t0 = tt * 32;
        const int kw = (tt == 7) ? 28 : 32;
        const int krows = (tt == 7) ? 32 : 36;
        #pragma unroll
        for (int p = 0; p < 10; p++) {
            int idx = tid + p * 320;
            u32 val = 0;
            if (idx < 96 * 32) {
                int k = idx / 96, u = idx - k * 96;
                if (u < VQ_ && k < kw) val = tf32u(Qc[(long)(t0 + k) * VQ_ + u]);
            }
            qr[p] = val;
        }
        #pragma unroll
        for (int p = 0; p < 7; p++) {
            int idx = tid + p * 320;
            u32 val = 0;
            if (idx < 36 * 56) {
                int k = idx / 56, v = idx - k * 56;
                if (v < VK_ && k < krows) val = tf32u(Kc[(long)(t0 + k) * VK_ + v]);
            }
            kr[p] = val;
        }
    };
    auto storeregs = [&](int buf) {
        #pragma unroll
        for (int p = 0; p < 10; p++) {
            int idx = tid + p * 320;
            if (idx < 96 * 32) {
                int k = idx / 96, u = idx - k * 96;
                Qs[buf][u * 36 + k] = qr[p];
            }
        }
        #pragma unroll
        for (int p = 0; p < 7; p++) {
            int idx = tid + p * 320;
            if (idx < 36 * 56) {
                int k = idx / 56, v = idx - k * 56;
                Ks[buf][k * 57 + v] = kr[p];
            }
        }
    };

    float acc[3][7][4];
    #pragma unroll
    for (int i = 0; i < 3; i++)
        #pragma unroll
        for (int j = 0; j < 7; j++)
            #pragma unroll
            for (int e = 0; e < 4; e++) acc[i][j][e] = 0.f;

    const int NT = CPB * 8;
    loadregs(0);
    storeregs(0);
    __syncthreads();

    for (int it = 0; it < NT; it++) {
        const int buf = it & 1;
        if (it + 1 < NT) loadregs(it + 1);
        const u32* Qsb = Qs[buf];
        const u32* Ksb = Ks[buf];
        #pragma unroll
        for (int k8 = 0; k8 < 4; k8++) {
            const int k0 = k8 * 8;
            u32 a[3][4], b[7][2];
            #pragma unroll
            for (int i = 0; i < 3; i++) {
                int u = uh * 48 + i * 16 + g;
                a[i][0] = Qsb[u * 36 + k0 + tg];
                a[i][1] = Qsb[(u + 8) * 36 + k0 + tg];
                a[i][2] = Qsb[u * 36 + k0 + tg + 4];
                a[i][3] = Qsb[(u + 8) * 36 + k0 + tg + 4];
            }
            #pragma unroll
            for (int j = 0; j < 7; j++) {
                b[j][0] = Ksb[(k0 + tg + l) * 57 + j * 8 + g];
                b[j][1] = Ksb[(k0 + tg + 4 + l) * 57 + j * 8 + g];
            }
            #pragma unroll
            for (int i = 0; i < 3; i++)
                #pragma unroll
                for (int j = 0; j < 7; j++) mma8(acc[i][j], a[i], b[j]);
        }
        if (it + 1 < NT) storeregs(buf ^ 1);
        __syncthreads();
    }

    float* pb = part + (((long)ksb * NS_ + ns) * 5 + l) * (VQ_ * VK_);
    #pragma unroll
    for (int i = 0; i < 3; i++) {
        #pragma unroll
        for (int j = 0; j < 7; j++) {
            int u = uh * 48 + i * 16 + g;
            int v = j * 8 + 2 * tg;
            if (v < VK_) {
                if (u < VQ_) {
                    pb[u * VK_ + v]     = acc[i][j][0];
                    pb[u * VK_ + v + 1] = acc[i][j][1];
                }
                if (u + 8 < VQ_) {
                    pb[(u + 8) * VK_ + v]     = acc[i][j][2];
                    pb[(u + 8) * VK_ + v + 1] = acc[i][j][3];
                }
            }
        }
    }
}

// ---------------- combine lags + softmax over VK -----------------------------
__global__ __launch_bounds__(64)
void softmax_kernel(const float* __restrict__ part, float* __restrict__ att)
{
    const int row = blockIdx.x;
    const int ns = row / VQ_;
    const int u  = row - ns * VQ_;
    const int tid = threadIdx.x;
    const float inv_scale = rsqrtf((float)KTOT);

    __shared__ float red[64];
    float val = -1e30f;
    if (tid < VK_) {
        float mx = -1e30f, sm = 0.f;
        #pragma unroll
        for (int l = 0; l <= L_; l++) {
            float s = 0.f;
            #pragma unroll
            for (int ks = 0; ks < KSPLIT; ks++)
                s += part[((((long)ks * NS_ + ns) * 5 + l) * VQ_ + u) * VK_ + tid];
            mx = fmaxf(mx, s);
            sm += s;
        }
        val = 0.5f * (mx + sm * 0.2f) * inv_scale;
    }
    red[tid] = val; __syncthreads();
    for (int s = 32; s > 0; s >>= 1) {
        if (tid < s) red[tid] = fmaxf(red[tid], red[tid + s]);
        __syncthreads();
    }
    float rmax = red[0]; __syncthreads();
    float e = (tid < VK_) ? expf(val - rmax) : 0.f;
    red[tid] = e; __syncthreads();
    for (int s = 32; s > 0; s >>= 1) {
        if (tid < s) red[tid] += red[tid + s];
        __syncthreads();
    }
    float rsum = red[0];
    if (tid < VK_) att[(long)row * VK_ + tid] = e / rsum;
}

// ---------------- y = att @ V via mma.sync tf32 (unchanged) ------------------
#define YG_SMEM ((56*136 + 56*104) * 4)
__global__ __launch_bounds__(256)
void ygemm_mma(const float* __restrict__ Vp, const float* __restrict__ att,
               float* __restrict__ y)
{
    extern __shared__ u32 dynsh[];
    u32* Vs = dynsh;
    u32* Bs = dynsh + 56 * 136;

    const int ct0 = blockIdx.x * 128;
    const int ns  = blockIdx.y;
    const int n   = ns >> 2;
    const float* A = Vp + (long)n * VP_PER_N + (long)ct0 * VK_;
    const float* B = att + (long)ns * (VQ_ * VK_);
    float* Yb = y + (long)ns * Y_PER_NS;

    const int tid = threadIdx.x, w = tid >> 5, lane = tid & 31;
    const int g = lane >> 2, tg = lane & 3;
    const int mw = (w & 3) * 32, nw = (w >> 2) * 48;

    for (int idx = tid; idx < 128 * 56; idx += 256) {
        int ct = idx / 56, k = idx - (idx / 56) * 56;
        Vs[k * 136 + ct] = (k < VK_) ? tf32u(A[ct * VK_ + k]) : 0u;
    }
    for (int idx = tid; idx < 96 * 56; idx += 256) {
        int vq = idx / 56, k = idx - (idx / 56) * 56;
        Bs[k * 104 + vq] = (k < VK_ && vq < VQ_) ? tf32u(B[vq * VK_ + k]) : 0u;
    }
    __syncthreads();

    float acc[2][6][4];
    #pragma unroll
    for (int i = 0; i < 2; i++)
        #pragma unroll
        for (int j = 0; j < 6; j++)
            #pragma unroll
            for (int e = 0; e < 4; e++) acc[i][j][e] = 0.f;

    #pragma unroll
    for (int kq = 0; kq < 7; kq++) {
        const int k0 = kq * 8;
        u32 a[2][4];
        #pragma unroll
        for (int mi = 0; mi < 2; mi++) {
            int m = mw + mi * 16;
            a[mi][0] = Vs[(k0 + tg) * 136 + m + g];
            a[mi][1] = Vs[(k0 + tg) * 136 + m + g + 8];
            a[mi][2] = Vs[(k0 + tg + 4) * 136 + m + g];
            a[mi][3] = Vs[(k0 + tg + 4) * 136 + m + g + 8];
        }
        #pragma unroll
        for (int ji = 0; ji < 6; ji++) {
            u32 b[2];
            b[0] = Bs[(k0 + tg) * 104 + nw + ji * 8 + g];
            b[1] = Bs[(k0 + tg + 4) * 104 + nw + ji * 8 + g];
            mma8(acc[0][ji], a[0], b);
            mma8(acc[1][ji], a[1], b);
        }
    }
    #pragma unroll
    for (int mi = 0; mi < 2; mi++) {
        int ct = ct0 + mw + mi * 16 + g;
        #pragma unroll
        for (int ji = 0; ji < 6; ji++) {
            int vq = nw + ji * 8 + 2 * tg;
            if (vq < VQ_) {
                float2 o0; o0.x = acc[mi][ji][0]; o0.y = acc[mi][ji][1];
                float2 o1; o1.x = acc[mi][ji][2]; o1.y = acc[mi][ji][3];
                *(float2*)&Yb[(long)ct * VQ_ + vq] = o0;
                *(float2*)&Yb[(long)(ct + 8) * VQ_ + vq] = o1;
            }
        }
    }
}

// ---------------- batchnorm + epilogue (unchanged) ---------------------------
__global__ __launch_bounds__(256)
void bn_partial(const float* __restrict__ z, const float* __restrict__ d,
                float* __restrict__ partials)
{
    const int c = blockIdx.x, n = blockIdx.y, which = blockIdx.z;
    const float* src = (which ? d : z) + (long)(n * C_ + c) * SPO;
    float s1 = 0.f, s2 = 0.f;
    for (int i = threadIdx.x; i < SPO; i += 256) {
        float v = src[i];
        s1 += v; s2 += v * v;
    }
    __shared__ float r1[256], r2[256];
    int tid = threadIdx.x;
    r1[tid] = s1; r2[tid] = s2; __syncthreads();
    for (int s = 128; s > 0; s >>= 1) {
        if (tid < s) { r1[tid] += r1[tid + s]; r2[tid] += r2[tid + s]; }
        __syncthreads();
    }
    if (tid == 0) {
        partials[((which * C_ + c) * N_ + n) * 2 + 0] = r1[0];
        partials[((which * C_ + c) * N_ + n) * 2 + 1] = r2[0];
    }
}

__global__ __launch_bounds__(128)
void bn_final(const float* __restrict__ partials,
              const float* __restrict__ gz, const float* __restrict__ bz,
              const float* __restrict__ gd, const float* __restrict__ bd,
              float* __restrict__ coef)
{
    int tid = threadIdx.x;
    if (tid >= 128) return;
    int which = tid >> 6, c = tid & 63;
    float s1 = 0.f, s2 = 0.f;
    for (int n = 0; n < N_; n++) {
        s1 += partials[((which * C_ + c) * N_ + n) * 2 + 0];
        s2 += partials[((which * C_ + c) * N_ + n) * 2 + 1];
    }
    float inv = 1.0f / (float)BN_COUNT;
    float mean = s1 * inv;
    float var  = s2 * inv - mean * mean;
    float rstd = rsqrtf(var + 1e-5f);
    float g = which ? gd[c] : gz[c];
    float b = which ? bd[c] : bz[c];
    float a = g * rstd;
    coef[tid * 2 + 0] = a;
    coef[tid * 2 + 1] = b - mean * a;
}

__global__ __launch_bounds__(256)
void final_kernel(const float* __restrict__ z, const float* __restrict__ d,
                  const float* __restrict__ coef, float* __restrict__ out)
{
    long i = (long)blockIdx.x * 256 + threadIdx.x;
    if (i >= OUT_TOTAL) return;
    int c = (int)((i / SPO) & (C_ - 1));
    float az = coef[c * 2], bz_ = coef[c * 2 + 1];
    float ad = coef[(C_ + c) * 2], bd_ = coef[(C_ + c) * 2 + 1];
    float v = fmaf(az, z[i], bz_) + fmaf(ad, d[i], bd_);
    out[i] = v > 0.f ? v : 0.1f * v;
}

// ---------------- launch -----------------------------------------------------
extern "C" void kernel_launch(void* const* d_in, const int* in_sizes, int n_in,
                              void* d_out, int out_size)
{
    const float* x_q   = (const float*)d_in[0];
    const float* x_k   = (const float*)d_in[1];
    const float* x_v   = (const float*)d_in[2];
    const float* Wq    = (const float*)d_in[3];
    const float* bq    = (const float*)d_in[4];
    const float* Wk    = (const float*)d_in[5];
    const float* bk    = (const float*)d_in[6];
    const float* Wv    = (const float*)d_in[7];
    const float* bv    = (const float*)d_in[8];
    const float* Wout  = (const float*)d_in[9];
    const float* bout  = (const float*)d_in[10];
    const float* gout  = (const float*)d_in[11];
    const float* bnout = (const float*)d_in[12];
    const float* Wdown = (const float*)d_in[13];
    const float* bdown = (const float*)d_in[14];
    const float* gdown = (const float*)d_in[15];
    const float* bndwn = (const float*)d_in[16];

    float *Qp, *Kp, *Vp, *part, *att, *y, *z, *dd, *bnp, *coef;
    cudaGetSymbolAddress((void**)&Qp,   g_Qp);
    cudaGetSymbolAddress((void**)&Kp,   g_Kp);
    cudaGetSymbolAddress((void**)&Vp,   g_Vp);
    cudaGetSymbolAddress((void**)&part, g_part);
    cudaGetSymbolAddress((void**)&att,  g_att);
    cudaGetSymbolAddress((void**)&y,    g_y);
    cudaGetSymbolAddress((void**)&z,    g_z);
    cudaGetSymbolAddress((void**)&dd,   g_d);
    cudaGetSymbolAddress((void**)&bnp,  g_bnpart);
    cudaGetSymbolAddress((void**)&coef, g_bncoef);

    cudaFuncSetAttribute(ygemm_mma, cudaFuncAttributeMaxDynamicSharedMemorySize, YG_SMEM);

    // projections (tensor-core, pipelined)
    conv_mma<<<dim3(89, 4, N_), 256>>>(Wq, bq, x_q, Qp, 256, 64, SPQ, SPO, 1474560L, 5806080L);
    conv_mma<<<dim3(50, 4, N_), 256>>>(Wk, bk, x_k, Kp, 256, 64, SPK, SPK, 819200L, 3276800L);
    conv_mma<<<dim3(50, 1, N_), 256>>>(Wv, bv, x_v, Vp, 64, 64, SPK, SPK, 819200L, 819200L);
    conv_mma<<<dim3(90, 1, N_), 256>>>(Wdown, bdown, x_q, dd, 64, 64, SPO, SPO, 1474560L, 1474560L);

    // tensor-core multi-lag scores (pipelined, 256 blocks) + softmax
    score_mma<<<dim3(NS_, KSPLIT), 320>>>(Qp, Kp, part);
    softmax_kernel<<<NS_ * VQ_, 64>>>(part, att);

    // y = att @ V (tensor-core), out projection (tensor-core)
    ygemm_mma<<<dim3(128, NS_), 256, YG_SMEM>>>(Vp, att, y);
    conv_mma<<<dim3(90, 1, N_), 256>>>(Wout, bout, y, z, 64, 256, SPO, SPO, 5898240L, 1474560L);

    // batchnorm + fused epilogue
    bn_partial<<<dim3(C_, N_, 2), 256>>>(z, dd, bnp);
    bn_final<<<1, 128>>>(bnp, gout, bnout, gdown, bndwn, coef);
    final_kernel<<<(OUT_TOTAL + 255) / 256, 256>>>(z, dd, coef, (float*)d_out);
}

// round 13
// speedup vs baseline: 3.4855x; 2.0414x over previous
#include <cuda_runtime.h>
#include <cuda_bf16.h>
#include <math.h>

#define N_   8
#define C_   64
#define T_   256
#define VQ_  90
#define VK_  50
#define S_   4
#define L_   4
#define Tq_  252
#define SC_  256
#define NS_  32
#define KSPLIT 8
#define CPB   8
#define KTOT 16128

#define KP_PER_NS  819200
#define VP_PER_N   819200
#define Y_PER_NS   1474560
#define SPQ  22680
#define SPK  12800
#define SPO  23040
#define OUT_TOTAL 11796480
#define BN_COUNT  184320

typedef unsigned long long u64;
typedef unsigned int u32;

// ---- tf32 mma.sync helpers (base PTX, validated R9-R11) ---------------------
__device__ __forceinline__ u32 tf32u(float x) {
    u32 r; asm("cvt.rna.tf32.f32 %0, %1;" : "=r"(r) : "f"(x)); return r;
}
__device__ __forceinline__ u32 tf32s(u32 raw) {   // cvt from staged raw f32 bits
    u32 r; asm("cvt.rna.tf32.f32 %0, %1;" : "=r"(r) : "f"(__uint_as_float(raw)));
    return r;
}
__device__ __forceinline__ void mma8(float* c, const u32* a, const u32* b) {
    asm volatile("mma.sync.aligned.m16n8k8.row.col.f32.tf32.tf32.f32 "
        "{%0,%1,%2,%3}, {%4,%5,%6,%7}, {%8,%9}, {%0,%1,%2,%3};"
        : "+f"(c[0]), "+f"(c[1]), "+f"(c[2]), "+f"(c[3])
        : "r"(a[0]), "r"(a[1]), "r"(a[2]), "r"(a[3]), "r"(b[0]), "r"(b[1]));
}
__device__ __forceinline__ u32 smem_u32(const void* p) {
    u32 a; asm("{ .reg .u64 t; cvta.to.shared.u64 t, %1; cvt.u32.u64 %0, t; }" : "=r"(a) : "l"(p));
    return a;
}
__device__ __forceinline__ void cpa16(u32 dst, const void* src, u32 bytes) {
    asm volatile("cp.async.ca.shared.global [%0], [%1], 16, %2;" :: "r"(dst), "l"(src), "r"(bytes));
}
__device__ __forceinline__ void cpa8(u32 dst, const void* src, u32 bytes) {
    asm volatile("cp.async.ca.shared.global [%0], [%1], 8, %2;" :: "r"(dst), "l"(src), "r"(bytes));
}
__device__ __forceinline__ void cpa_commit() { asm volatile("cp.async.commit_group;"); }
__device__ __forceinline__ void cpa_wait1() { asm volatile("cp.async.wait_group 1;" ::: "memory"); }
__device__ __forceinline__ void cpa_wait0() { asm volatile("cp.async.wait_group 0;" ::: "memory"); }

// ---------------- scratch ----------------------------------------------------
__device__ float g_Qp[(long)N_*SC_*Tq_*VQ_];
__device__ float g_Kp[(long)N_*SC_*T_*VK_];
__device__ float g_Vp[(long)N_*C_*T_*VK_];
__device__ float g_part[(long)KSPLIT*NS_*(L_+1)*VQ_*VK_];
__device__ float g_att[(long)NS_*VQ_*VK_];
__device__ float g_y[(long)N_*SC_*T_*VQ_];
__device__ float g_z[(long)OUT_TOTAL];
__device__ float g_d[(long)OUT_TOTAL];
__device__ float g_bnpart[2*C_*N_*2];
__device__ float g_bncoef[2*C_*2];

// ---------------- conv1x1 via mma.sync tf32, cp.async 3-stage ----------------
// Y[n][m][sp] = sum_k W[m][k] X[n][k][sp] + b[m]
// block 64m x 256n, BK=16, 256 thr (2 m-warps x 4 n-warps)
// smem/buf: Wm[64][20] m-major raw f32, Xs[16][264] k-major raw f32
#define CONV_BUF_W (64*20)
#define CONV_BUF_X (16*264)
#define CONV_BUF   (CONV_BUF_W + CONV_BUF_X)
#define CONV_SMEM  (3 * CONV_BUF * 4)
__global__ __launch_bounds__(256)
void conv_mma(const float* __restrict__ W, const float* __restrict__ bias,
              const float* __restrict__ X, float* __restrict__ Y,
              int M, int K, int Nsp, int ldx, long xbatch, long ybatch)
{
    extern __shared__ u32 cdyn[];
    const int n  = blockIdx.z;
    const int m0 = blockIdx.y * 64;
    const int n0 = blockIdx.x * 256;
    const float* Xn = X + (long)n * xbatch;
    float* Yn = Y + (long)n * ybatch;

    const int tid = threadIdx.x, w = tid >> 5, lane = tid & 31;
    const int g = lane >> 2, tg = lane & 3;
    const int mw = (w & 1) * 32, nw = (w >> 1) * 64;
    const int KT = K >> 4;
    const u32 smem0 = smem_u32(cdyn);

    const int wm = tid >> 2, wck = (tid & 3) * 4;   // this thread's W chunk

    auto issue = [&](int kt) {
        const u32 base = smem0 + (u32)(kt % 3) * (CONV_BUF * 4);
        const int k0 = kt * 16;
        cpa16(base + (wm * 20 + wck) * 4, &W[(long)(m0 + wm) * K + k0 + wck], 16);
        #pragma unroll
        for (int p = 0; p < 4; p++) {
            int i = p * 256 + tid;
            int kk = i >> 6, j4 = (i & 63) * 4;
            int col = n0 + j4;
            int bytes = (Nsp - col) * 4;
            bytes = bytes < 0 ? 0 : (bytes > 16 ? 16 : bytes);
            const float* src = &Xn[(long)(k0 + kk) * ldx + (col < Nsp ? col : 0)];
            cpa16(base + (CONV_BUF_W + kk * 264 + j4) * 4, src, (u32)bytes);
        }
        cpa_commit();
    };

    float acc[2][8][4];
    #pragma unroll
    for (int i = 0; i < 2; i++)
        #pragma unroll
        for (int j = 0; j < 8; j++)
            #pragma unroll
            for (int e = 0; e < 4; e++) acc[i][j][e] = 0.f;

    issue(0);
    if (KT > 1) issue(1);

    for (int kt = 0; kt < KT; kt++) {
        if (kt == KT - 1) cpa_wait0(); else cpa_wait1();
        __syncthreads();
        if (kt + 2 < KT) issue(kt + 2);
        const u32* Wb = cdyn + (kt % 3) * CONV_BUF;
        const u32* Xb = Wb + CONV_BUF_W;
        #pragma unroll
        for (int k8 = 0; k8 < 16; k8 += 8) {
            u32 a[2][4];
            #pragma unroll
            for (int mi = 0; mi < 2; mi++) {
                int m = mw + mi * 16;
                a[mi][0] = tf32s(Wb[(m + g) * 20 + k8 + tg]);
                a[mi][1] = tf32s(Wb[(m + g + 8) * 20 + k8 + tg]);
                a[mi][2] = tf32s(Wb[(m + g) * 20 + k8 + tg + 4]);
                a[mi][3] = tf32s(Wb[(m + g + 8) * 20 + k8 + tg + 4]);
            }
            #pragma unroll
            for (int ji = 0; ji < 8; ji++) {
                u32 b[2];
                b[0] = tf32s(Xb[(k8 + tg) * 264 + nw + ji * 8 + g]);
                b[1] = tf32s(Xb[(k8 + tg + 4) * 264 + nw + ji * 8 + g]);
                mma8(acc[0][ji], a[0], b);
                mma8(acc[1][ji], a[1], b);
            }
        }
        __syncthreads();
    }

    #pragma unroll
    for (int mi = 0; mi < 2; mi++) {
        int mrow = m0 + mw + mi * 16 + g;
        float bv0 = bias[mrow], bv1 = bias[mrow + 8];
        #pragma unroll
        for (int ji = 0; ji < 8; ji++) {
            int col = n0 + nw + ji * 8 + 2 * tg;
            if (col < Nsp) {
                float2 o0; o0.x = acc[mi][ji][0] + bv0; o0.y = acc[mi][ji][1] + bv0;
                float2 o1; o1.x = acc[mi][ji][2] + bv1; o1.y = acc[mi][ji][3] + bv1;
                *(float2*)&Yn[(long)mrow * Nsp + col] = o0;
                *(float2*)&Yn[(long)(mrow + 8) * Nsp + col] = o1;
            }
        }
    }
}

// ---------------- tf32 mma.sync score kernel, cp.async 3-stage ---------------
// D_l[u][v] = sum_{c,t} Qp[ns][c][t][u] * Kp[ns][c][t+l][v]
// grid (ns=32, ksplit=8): 8 c per block, 64 k-tiles of 32.
// smem/buf: Qk[32k][104u] raw f32 (k-major), Ks[36k][72v] raw f32
#define SC_BUF_Q (32*104)
#define SC_BUF_K (36*72)
#define SC_BUF   (SC_BUF_Q + SC_BUF_K)
#define SC_SMEM  (3 * SC_BUF * 4)
__global__ __launch_bounds__(320)
void score_mma(const float* __restrict__ Qp, const float* __restrict__ Kp,
               float* __restrict__ part)
{
    extern __shared__ u32 sdyn[];
    const int ns = blockIdx.x, ksb = blockIdx.y;
    const int tid = threadIdx.x, w = tid >> 5, lane = tid & 31;
    const int g = lane >> 2, tg = lane & 3;
    const int l = w >> 1, uh = w & 1;
    const float* Qb = Qp + (long)ns * 1451520;
    const float* Kb = Kp + (long)ns * KP_PER_NS;
    const u32 smem0 = smem_u32(sdyn);

    // per-thread cp.async chunk descriptors (fixed across tiles)
    int qk_[5], qso_[5], qdo_[5];
    #pragma unroll
    for (int p = 0; p < 5; p++) {
        int idx = tid + p * 320;
        if (idx < 32 * 45) {
            int k = idx / 45, c45 = idx - k * 45;
            qk_[p] = k; qso_[p] = k * VQ_ + c45 * 2; qdo_[p] = k * 104 + c45 * 2;
        } else qk_[p] = -1;
    }
    int kk_[3], kso_[3], kdo_[3];
    #pragma unroll
    for (int p = 0; p < 3; p++) {
        int idx = tid + p * 320;
        if (idx < 36 * 25) {
            int k = idx / 25, c25 = idx - k * 25;
            kk_[p] = k; kso_[p] = k * VK_ + c25 * 2; kdo_[p] = SC_BUF_Q + k * 72 + c25 * 2;
        } else kk_[p] = -1;
    }

    auto issue = [&](int it) {
        const int c = ksb * CPB + (it >> 3), tt = it & 7;
        const int t0 = tt * 32;
        const int kw = (tt == 7) ? 28 : 32;
        const int krows = (tt == 7) ? 32 : 36;
        const u32 base = smem0 + (u32)(it % 3) * (SC_BUF * 4);
        const float* Qsrc = Qb + (long)c * SPQ + (long)t0 * VQ_;
        const float* Ksrc = Kb + (long)c * SPK + (long)t0 * VK_;
        #pragma unroll
        for (int p = 0; p < 5; p++) {
            if (qk_[p] >= 0) {
                u32 sz = (qk_[p] < kw) ? 8u : 0u;
                cpa8(base + qdo_[p] * 4, sz ? (Qsrc + qso_[p]) : Qb, sz);
            }
        }
        #pragma unroll
        for (int p = 0; p < 3; p++) {
            if (kk_[p] >= 0) {
                u32 sz = (kk_[p] < krows) ? 8u : 0u;
                cpa8(base + kdo_[p] * 4, sz ? (Ksrc + kso_[p]) : Kb, sz);
            }
        }
        cpa_commit();
    };

    float acc[3][7][4];
    #pragma unroll
    for (int i = 0; i < 3; i++)
        #pragma unroll
        for (int j = 0; j < 7; j++)
            #pragma unroll
            for (int e = 0; e < 4; e++) acc[i][j][e] = 0.f;

    const int NT = CPB * 8;
    issue(0); issue(1);

    for (int it = 0; it < NT; it++) {
        if (it == NT - 1) cpa_wait0(); else cpa_wait1();
        __syncthreads();
        if (it + 2 < NT) issue(it + 2);
        const u32* Qsb = sdyn + (it % 3) * SC_BUF;
        const u32* Ksb = Qsb + SC_BUF_Q;
        #pragma unroll
        for (int k8 = 0; k8 < 4; k8++) {
            const int k0 = k8 * 8;
            u32 a[3][4], b[7][2];
            #pragma unroll
            for (int i = 0; i < 3; i++) {
                int u = uh * 48 + i * 16 + g;
                a[i][0] = tf32s(Qsb[(k0 + tg) * 104 + u]);
                a[i][1] = tf32s(Qsb[(k0 + tg) * 104 + u + 8]);
                a[i][2] = tf32s(Qsb[(k0 + tg + 4) * 104 + u]);
                a[i][3] = tf32s(Qsb[(k0 + tg + 4) * 104 + u + 8]);
            }
            #pragma unroll
            for (int j = 0; j < 7; j++) {
                b[j][0] = tf32s(Ksb[(k0 + tg + l) * 72 + j * 8 + g]);
                b[j][1] = tf32s(Ksb[(k0 + tg + 4 + l) * 72 + j * 8 + g]);
            }
            #pragma unroll
            for (int i = 0; i < 3; i++)
                #pragma unroll
                for (int j = 0; j < 7; j++) mma8(acc[i][j], a[i], b[j]);
        }
        __syncthreads();
    }

    float* pb = part + (((long)ksb * NS_ + ns) * 5 + l) * (VQ_ * VK_);
    #pragma unroll
    for (int i = 0; i < 3; i++) {
        #pragma unroll
        for (int j = 0; j < 7; j++) {
            int u = uh * 48 + i * 16 + g;
            int v = j * 8 + 2 * tg;
            if (v < VK_) {
                if (u < VQ_) {
                    pb[u * VK_ + v]     = acc[i][j][0];
                    pb[u * VK_ + v + 1] = acc[i][j][1];
                }
                if (u + 8 < VQ_) {
                    pb[(u + 8) * VK_ + v]     = acc[i][j][2];
                    pb[(u + 8) * VK_ + v + 1] = acc[i][j][3];
                }
            }
        }
    }
}

// ---------------- combine lags + softmax over VK -----------------------------
__global__ __launch_bounds__(64)
void softmax_kernel(const float* __restrict__ part, float* __restrict__ att)
{
    const int row = blockIdx.x;
    const int ns = row / VQ_;
    const int u  = row - ns * VQ_;
    const int tid = threadIdx.x;
    const float inv_scale = rsqrtf((float)KTOT);

    __shared__ float red[64];
    float val = -1e30f;
    if (tid < VK_) {
        float mx = -1e30f, sm = 0.f;
        #pragma unroll
        for (int l = 0; l <= L_; l++) {
            float s = 0.f;
            #pragma unroll
            for (int ks = 0; ks < KSPLIT; ks++)
                s += part[((((long)ks * NS_ + ns) * 5 + l) * VQ_ + u) * VK_ + tid];
            mx = fmaxf(mx, s);
            sm += s;
        }
        val = 0.5f * (mx + sm * 0.2f) * inv_scale;
    }
    red[tid] = val; __syncthreads();
    for (int s = 32; s > 0; s >>= 1) {
        if (tid < s) red[tid] = fmaxf(red[tid], red[tid + s]);
        __syncthreads();
    }
    float rmax = red[0]; __syncthreads();
    float e = (tid < VK_) ? expf(val - rmax) : 0.f;
    red[tid] = e; __syncthreads();
    for (int s = 32; s > 0; s >>= 1) {
        if (tid < s) red[tid] += red[tid + s];
        __syncthreads();
    }
    float rsum = red[0];
    if (tid < VK_) att[(long)row * VK_ + tid] = e / rsum;
}

// ---------------- y = att @ V via mma.sync tf32 (unchanged) ------------------
#define YG_SMEM ((56*136 + 56*104) * 4)
__global__ __launch_bounds__(256)
void ygemm_mma(const float* __restrict__ Vp, const float* __restrict__ att,
               float* __restrict__ y)
{
    extern __shared__ u32 dynsh[];
    u32* Vs = dynsh;
    u32* Bs = dynsh + 56 * 136;

    const int ct0 = blockIdx.x * 128;
    const int ns  = blockIdx.y;
    const int n   = ns >> 2;
    const float* A = Vp + (long)n * VP_PER_N + (long)ct0 * VK_;
    const float* B = att + (long)ns * (VQ_ * VK_);
    float* Yb = y + (long)ns * Y_PER_NS;

    const int tid = threadIdx.x, w = tid >> 5, lane = tid & 31;
    const int g = lane >> 2, tg = lane & 3;
    const int mw = (w & 3) * 32, nw = (w >> 2) * 48;

    for (int idx = tid; idx < 128 * 56; idx += 256) {
        int ct = idx / 56, k = idx - (idx / 56) * 56;
        Vs[k * 136 + ct] = (k < VK_) ? tf32u(A[ct * VK_ + k]) : 0u;
    }
    for (int idx = tid; idx < 96 * 56; idx += 256) {
        int vq = idx / 56, k = idx - (idx / 56) * 56;
        Bs[k * 104 + vq] = (k < VK_ && vq < VQ_) ? tf32u(B[vq * VK_ + k]) : 0u;
    }
    __syncthreads();

    float acc[2][6][4];
    #pragma unroll
    for (int i = 0; i < 2; i++)
        #pragma unroll
        for (int j = 0; j < 6; j++)
            #pragma unroll
            for (int e = 0; e < 4; e++) acc[i][j][e] = 0.f;

    #pragma unroll
    for (int kq = 0; kq < 7; kq++) {
        const int k0 = kq * 8;
        u32 a[2][4];
        #pragma unroll
        for (int mi = 0; mi < 2; mi++) {
            int m = mw + mi * 16;
            a[mi][0] = Vs[(k0 + tg) * 136 + m + g];
            a[mi][1] = Vs[(k0 + tg) * 136 + m + g + 8];
            a[mi][2] = Vs[(k0 + tg + 4) * 136 + m + g];
            a[mi][3] = Vs[(k0 + tg + 4) * 136 + m + g + 8];
        }
        #pragma unroll
        for (int ji = 0; ji < 6; ji++) {
            u32 b[2];
            b[0] = Bs[(k0 + tg) * 104 + nw + ji * 8 + g];
            b[1] = Bs[(k0 + tg + 4) * 104 + nw + ji * 8 + g];
            mma8(acc[0][ji], a[0], b);
            mma8(acc[1][ji], a[1], b);
        }
    }
    #pragma unroll
    for (int mi = 0; mi < 2; mi++) {
        int ct = ct0 + mw + mi * 16 + g;
        #pragma unroll
        for (int ji = 0; ji < 6; ji++) {
            int vq = nw + ji * 8 + 2 * tg;
            if (vq < VQ_) {
                float2 o0; o0.x = acc[mi][ji][0]; o0.y = acc[mi][ji][1];
                float2 o1; o1.x = acc[mi][ji][2]; o1.y = acc[mi][ji][3];
                *(float2*)&Yb[(long)ct * VQ_ + vq] = o0;
                *(float2*)&Yb[(long)(ct + 8) * VQ_ + vq] = o1;
            }
        }
    }
}

// ---------------- batchnorm + epilogue (unchanged) ---------------------------
__global__ __launch_bounds__(256)
void bn_partial(const float* __restrict__ z, const float* __restrict__ d,
                float* __restrict__ partials)
{
    const int c = blockIdx.x, n = blockIdx.y, which = blockIdx.z;
    const float* src = (which ? d : z) + (long)(n * C_ + c) * SPO;
    float s1 = 0.f, s2 = 0.f;
    for (int i = threadIdx.x; i < SPO; i += 256) {
        float v = src[i];
        s1 += v; s2 += v * v;
    }
    __shared__ float r1[256], r2[256];
    int tid = threadIdx.x;
    r1[tid] = s1; r2[tid] = s2; __syncthreads();
    for (int s = 128; s > 0; s >>= 1) {
        if (tid < s) { r1[tid] += r1[tid + s]; r2[tid] += r2[tid + s]; }
        __syncthreads();
    }
    if (tid == 0) {
        partials[((which * C_ + c) * N_ + n) * 2 + 0] = r1[0];
        partials[((which * C_ + c) * N_ + n) * 2 + 1] = r2[0];
    }
}

__global__ __launch_bounds__(128)
void bn_final(const float* __restrict__ partials,
              const float* __restrict__ gz, const float* __restrict__ bz,
              const float* __restrict__ gd, const float* __restrict__ bd,
              float* __restrict__ coef)
{
    int tid = threadIdx.x;
    if (tid >= 128) return;
    int which = tid >> 6, c = tid & 63;
    float s1 = 0.f, s2 = 0.f;
    for (int n = 0; n < N_; n++) {
        s1 += partials[((which * C_ + c) * N_ + n) * 2 + 0];
        s2 += partials[((which * C_ + c) * N_ + n) * 2 + 1];
    }
    float inv = 1.0f / (float)BN_COUNT;
    float mean = s1 * inv;
    float var  = s2 * inv - mean * mean;
    float rstd = rsqrtf(var + 1e-5f);
    float g = which ? gd[c] : gz[c];
    float b = which ? bd[c] : bz[c];
    float a = g * rstd;
    coef[tid * 2 + 0] = a;
    coef[tid * 2 + 1] = b - mean * a;
}

__global__ __launch_bounds__(256)
void final_kernel(const float* __restrict__ z, const float* __restrict__ d,
                  const float* __restrict__ coef, float* __restrict__ out)
{
    long i = (long)blockIdx.x * 256 + threadIdx.x;
    if (i >= OUT_TOTAL) return;
    int c = (int)((i / SPO) & (C_ - 1));
    float az = coef[c * 2], bz_ = coef[c * 2 + 1];
    float ad = coef[(C_ + c) * 2], bd_ = coef[(C_ + c) * 2 + 1];
    float v = fmaf(az, z[i], bz_) + fmaf(ad, d[i], bd_);
    out[i] = v > 0.f ? v : 0.1f * v;
}

// ---------------- launch -----------------------------------------------------
extern "C" void kernel_launch(void* const* d_in, const int* in_sizes, int n_in,
                              void* d_out, int out_size)
{
    const float* x_q   = (const float*)d_in[0];
    const float* x_k   = (const float*)d_in[1];
    const float* x_v   = (const float*)d_in[2];
    const float* Wq    = (const float*)d_in[3];
    const float* bq    = (const float*)d_in[4];
    const float* Wk    = (const float*)d_in[5];
    const float* bk    = (const float*)d_in[6];
    const float* Wv    = (const float*)d_in[7];
    const float* bv    = (const float*)d_in[8];
    const float* Wout  = (const float*)d_in[9];
    const float* bout  = (const float*)d_in[10];
    const float* gout  = (const float*)d_in[11];
    const float* bnout = (const float*)d_in[12];
    const float* Wdown = (const float*)d_in[13];
    const float* bdown = (const float*)d_in[14];
    const float* gdown = (const float*)d_in[15];
    const float* bndwn = (const float*)d_in[16];

    float *Qp, *Kp, *Vp, *part, *att, *y, *z, *dd, *bnp, *coef;
    cudaGetSymbolAddress((void**)&Qp,   g_Qp);
    cudaGetSymbolAddress((void**)&Kp,   g_Kp);
    cudaGetSymbolAddress((void**)&Vp,   g_Vp);
    cudaGetSymbolAddress((void**)&part, g_part);
    cudaGetSymbolAddress((void**)&att,  g_att);
    cudaGetSymbolAddress((void**)&y,    g_y);
    cudaGetSymbolAddress((void**)&z,    g_z);
    cudaGetSymbolAddress((void**)&dd,   g_d);
    cudaGetSymbolAddress((void**)&bnp,  g_bnpart);
    cudaGetSymbolAddress((void**)&coef, g_bncoef);

    cudaFuncSetAttribute(conv_mma,  cudaFuncAttributeMaxDynamicSharedMemorySize, CONV_SMEM);
    cudaFuncSetAttribute(score_mma, cudaFuncAttributeMaxDynamicSharedMemorySize, SC_SMEM);
    cudaFuncSetAttribute(ygemm_mma, cudaFuncAttributeMaxDynamicSharedMemorySize, YG_SMEM);

    // projections (tensor-core, cp.async pipelined)
    conv_mma<<<dim3(89, 4, N_), 256, CONV_SMEM>>>(Wq, bq, x_q, Qp, 256, 64, SPQ, SPO, 1474560L, 5806080L);
    conv_mma<<<dim3(50, 4, N_), 256, CONV_SMEM>>>(Wk, bk, x_k, Kp, 256, 64, SPK, SPK, 819200L, 3276800L);
    conv_mma<<<dim3(50, 1, N_), 256, CONV_SMEM>>>(Wv, bv, x_v, Vp, 64, 64, SPK, SPK, 819200L, 819200L);
    conv_mma<<<dim3(90, 1, N_), 256, CONV_SMEM>>>(Wdown, bdown, x_q, dd, 64, 64, SPO, SPO, 1474560L, 1474560L);

    // tensor-core multi-lag scores (cp.async pipelined) + softmax
    score_mma<<<dim3(NS_, KSPLIT), 320, SC_SMEM>>>(Qp, Kp, part);
    softmax_kernel<<<NS_ * VQ_, 64>>>(part, att);

    // y = att @ V (tensor-core), out projection (tensor-core)
    ygemm_mma<<<dim3(128, NS_), 256, YG_SMEM>>>(Vp, att, y);
    conv_mma<<<dim3(90, 1, N_), 256, CONV_SMEM>>>(Wout, bout, y, z, 64, 256, SPO, SPO, 5898240L, 1474560L);

    // batchnorm + fused epilogue
    bn_partial<<<dim3(C_, N_, 2), 256>>>(z, dd, bnp);
    bn_final<<<1, 128>>>(bnp, gout, bnout, gdown, bndwn, coef);
    final_kernel<<<(OUT_TOTAL + 255) / 256, 256>>>(z, dd, coef, (float*)d_out);
}

// round 15
// speedup vs baseline: 3.5957x; 1.0316x over previous
#include <cuda_runtime.h>
#include <cuda_bf16.h>
#include <math.h>

#define N_   8
#define C_   64
#define T_   256
#define VQ_  90
#define VK_  50
#define S_   4
#define L_   4
#define Tq_  252
#define SC_  256
#define NS_  32
#define KSPLIT 8
#define CPB   8
#define KTOT 16128

#define KP_PER_NS  819200
#define VP_PER_N   819200
#define Y_PER_NS   1474560
#define SPQ  22680
#define SPK  12800
#define SPO  23040
#define OUT_TOTAL 11796480
#define BN_COUNT  184320
#define NBLK_BN 720         // 90 sp-blocks * 8 n

typedef unsigned long long u64;
typedef unsigned int u32;

// ---- tf32 mma.sync helpers --------------------------------------------------
__device__ __forceinline__ u32 tf32u(float x) {
    u32 r; asm("cvt.rna.tf32.f32 %0, %1;" : "=r"(r) : "f"(x)); return r;
}
__device__ __forceinline__ u32 tf32s(u32 raw) {
    u32 r; asm("cvt.rna.tf32.f32 %0, %1;" : "=r"(r) : "f"(__uint_as_float(raw)));
    return r;
}
__device__ __forceinline__ void mma8(float* c, const u32* a, const u32* b) {
    asm volatile("mma.sync.aligned.m16n8k8.row.col.f32.tf32.tf32.f32 "
        "{%0,%1,%2,%3}, {%4,%5,%6,%7}, {%8,%9}, {%0,%1,%2,%3};"
        : "+f"(c[0]), "+f"(c[1]), "+f"(c[2]), "+f"(c[3])
        : "r"(a[0]), "r"(a[1]), "r"(a[2]), "r"(a[3]), "r"(b[0]), "r"(b[1]));
}
__device__ __forceinline__ u32 smem_u32(const void* p) {
    u32 a; asm("{ .reg .u64 t; cvta.to.shared.u64 t, %1; cvt.u32.u64 %0, t; }" : "=r"(a) : "l"(p));
    return a;
}
__device__ __forceinline__ void cpa16(u32 dst, const void* src, u32 bytes) {
    asm volatile("cp.async.ca.shared.global [%0], [%1], 16, %2;" :: "r"(dst), "l"(src), "r"(bytes));
}
__device__ __forceinline__ void cpa8(u32 dst, const void* src, u32 bytes) {
    asm volatile("cp.async.ca.shared.global [%0], [%1], 8, %2;" :: "r"(dst), "l"(src), "r"(bytes));
}
__device__ __forceinline__ void cpa_commit() { asm volatile("cp.async.commit_group;"); }
__device__ __forceinline__ void cpa_wait2() { asm volatile("cp.async.wait_group 2;" ::: "memory"); }
__device__ __forceinline__ void cpa_wait1() { asm volatile("cp.async.wait_group 1;" ::: "memory"); }
__device__ __forceinline__ void cpa_wait0() { asm volatile("cp.async.wait_group 0;" ::: "memory"); }

// ---------------- scratch ----------------------------------------------------
__device__ float g_Qp[(long)N_*SC_*Tq_*VQ_];
__device__ float g_Kp[(long)N_*SC_*T_*VK_];
__device__ float g_Vp[(long)N_*C_*T_*VK_];
__device__ float g_part[(long)KSPLIT*NS_*(L_+1)*VQ_*VK_];
__device__ float g_att[(long)NS_*VQ_*VK_];
__device__ float g_y[(long)N_*SC_*T_*VQ_];
__device__ float g_z[(long)OUT_TOTAL];
__device__ float g_d[(long)OUT_TOTAL];
__device__ float g_bnp2[2L*NBLK_BN*64*2];      // per-block (s1,s2) per channel
__device__ float g_bncoef[2*C_*2];

// ---------------- conv1x1 via mma.sync tf32, cp.async 4-stage ----------------
// Y[n][m][sp] = sum_k W[m][k] X[n][k][sp] + b[m]
// bnsum != null: also emit per-block per-channel (sum, sumsq) partials.
#define CONV_BUF_W (64*20)
#define CONV_BUF_X (16*264)
#define CONV_BUF   (CONV_BUF_W + CONV_BUF_X)
#define CONV_SMEM  (4 * CONV_BUF * 4)
__global__ __launch_bounds__(256, 2)
void conv_mma(const float* __restrict__ W, const float* __restrict__ bias,
              const float* __restrict__ X, float* __restrict__ Y,
              int M, int K, int Nsp, int ldx, long xbatch, long ybatch,
              float* bnsum)
{
    extern __shared__ u32 cdyn[];
    const int n  = blockIdx.z;
    const int m0 = blockIdx.y * 64;
    const int n0 = blockIdx.x * 256;
    const float* Xn = X + (long)n * xbatch;
    float* Yn = Y + (long)n * ybatch;

    const int tid = threadIdx.x, w = tid >> 5, lane = tid & 31;
    const int g = lane >> 2, tg = lane & 3;
    const int mw = (w & 1) * 32, nw = (w >> 1) * 64;
    const int KT = K >> 4;
    const u32 smem0 = smem_u32(cdyn);

    const int wm = tid >> 2, wck = (tid & 3) * 4;

    auto issue = [&](int kt) {
        const u32 base = smem0 + (u32)(kt & 3) * (CONV_BUF * 4);
        const int k0 = kt * 16;
        cpa16(base + (wm * 20 + wck) * 4, &W[(long)(m0 + wm) * K + k0 + wck], 16);
        #pragma unroll
        for (int p = 0; p < 4; p++) {
            int i = p * 256 + tid;
            int kk = i >> 6, j4 = (i & 63) * 4;
            int col = n0 + j4;
            int bytes = (Nsp - col) * 4;
            bytes = bytes < 0 ? 0 : (bytes > 16 ? 16 : bytes);
            const float* src = &Xn[(long)(k0 + kk) * ldx + (col < Nsp ? col : 0)];
            cpa16(base + (CONV_BUF_W + kk * 264 + j4) * 4, src, (u32)bytes);
        }
        cpa_commit();
    };

    float acc[2][8][4];
    #pragma unroll
    for (int i = 0; i < 2; i++)
        #pragma unroll
        for (int j = 0; j < 8; j++)
            #pragma unroll
            for (int e = 0; e < 4; e++) acc[i][j][e] = 0.f;

    issue(0);
    if (KT > 1) issue(1);
    if (KT > 2) issue(2);

    for (int kt = 0; kt < KT; kt++) {
        int rem = KT - kt - 1; rem = rem > 2 ? 2 : rem;
        if (rem == 2) cpa_wait2(); else if (rem == 1) cpa_wait1(); else cpa_wait0();
        __syncthreads();
        if (kt + 3 < KT) issue(kt + 3);
        const u32* Wb = cdyn + (kt & 3) * CONV_BUF;
        const u32* Xb = Wb + CONV_BUF_W;
        #pragma unroll
        for (int k8 = 0; k8 < 16; k8 += 8) {
            u32 a[2][4];
            #pragma unroll
            for (int mi = 0; mi < 2; mi++) {
                int m = mw + mi * 16;
                a[mi][0] = tf32s(Wb[(m + g) * 20 + k8 + tg]);
                a[mi][1] = tf32s(Wb[(m + g + 8) * 20 + k8 + tg]);
                a[mi][2] = tf32s(Wb[(m + g) * 20 + k8 + tg + 4]);
                a[mi][3] = tf32s(Wb[(m + g + 8) * 20 + k8 + tg + 4]);
            }
            #pragma unroll
            for (int ji = 0; ji < 8; ji++) {
                u32 b[2];
                b[0] = tf32s(Xb[(k8 + tg) * 264 + nw + ji * 8 + g]);
                b[1] = tf32s(Xb[(k8 + tg + 4) * 264 + nw + ji * 8 + g]);
                mma8(acc[0][ji], a[0], b);
                mma8(acc[1][ji], a[1], b);
            }
        }
        __syncthreads();
    }

    float s1l[4] = {0.f, 0.f, 0.f, 0.f}, s2l[4] = {0.f, 0.f, 0.f, 0.f};
    #pragma unroll
    for (int mi = 0; mi < 2; mi++) {
        int mrow = m0 + mw + mi * 16 + g;
        float bv0 = bias[mrow], bv1 = bias[mrow + 8];
        #pragma unroll
        for (int ji = 0; ji < 8; ji++) {
            int col = n0 + nw + ji * 8 + 2 * tg;
            if (col < Nsp) {
                float2 o0; o0.x = acc[mi][ji][0] + bv0; o0.y = acc[mi][ji][1] + bv0;
                float2 o1; o1.x = acc[mi][ji][2] + bv1; o1.y = acc[mi][ji][3] + bv1;
                *(float2*)&Yn[(long)mrow * Nsp + col] = o0;
                *(float2*)&Yn[(long)(mrow + 8) * Nsp + col] = o1;
                if (bnsum) {
                    s1l[mi * 2 + 0] += o0.x + o0.y;
                    s2l[mi * 2 + 0] += o0.x * o0.x + o0.y * o0.y;
                    s1l[mi * 2 + 1] += o1.x + o1.y;
                    s2l[mi * 2 + 1] += o1.x * o1.x + o1.y * o1.y;
                }
            }
        }
    }
    if (bnsum) {
        // quad reduce (lanes 4g..4g+3 share rows), then cross-warp via smem
        #pragma unroll
        for (int r = 0; r < 4; r++) {
            s1l[r] += __shfl_xor_sync(0xffffffffu, s1l[r], 1);
            s1l[r] += __shfl_xor_sync(0xffffffffu, s1l[r], 2);
            s2l[r] += __shfl_xor_sync(0xffffffffu, s2l[r], 1);
            s2l[r] += __shfl_xor_sync(0xffffffffu, s2l[r], 2);
        }
        float* bs = (float*)cdyn;   // [64 rows][4 nwarp][2]
        if (tg == 0) {
            #pragma unroll
            for (int r = 0; r < 4; r++) {
                int row = mw + (r >> 1) * 16 + g + (r & 1) * 8;
                bs[(row * 4 + (w >> 1)) * 2 + 0] = s1l[r];
                bs[(row * 4 + (w >> 1)) * 2 + 1] = s2l[r];
            }
        }
        __syncthreads();
        if (tid < 64) {
            float a1 = 0.f, a2 = 0.f;
            #pragma unroll
            for (int j = 0; j < 4; j++) {
                a1 += bs[(tid * 4 + j) * 2 + 0];
                a2 += bs[(tid * 4 + j) * 2 + 1];
            }
            int blk = blockIdx.x * gridDim.z + blockIdx.z;
            ((float2*)bnsum)[(long)blk * 64 + tid] = make_float2(a1, a2);
        }
    }
}

// ---------------- tf32 mma.sync score kernel, cp.async 4-stage ---------------
#define SC_BUF_Q (32*104)
#define SC_BUF_K (36*72)
#define SC_BUF   (SC_BUF_Q + SC_BUF_K)
#define SC_SMEM  (4 * SC_BUF * 4)
__global__ __launch_bounds__(320)
void score_mma(const float* __restrict__ Qp, const float* __restrict__ Kp,
               float* __restrict__ part)
{
    extern __shared__ u32 sdyn[];
    const int ns = blockIdx.x, ksb = blockIdx.y;
    const int tid = threadIdx.x, w = tid >> 5, lane = tid & 31;
    const int g = lane >> 2, tg = lane & 3;
    const int l = w >> 1, uh = w & 1;
    const float* Qb = Qp + (long)ns * 1451520;
    const float* Kb = Kp + (long)ns * KP_PER_NS;
    const u32 smem0 = smem_u32(sdyn);

    int qk_[5], qso_[5], qdo_[5];
    #pragma unroll
    for (int p = 0; p < 5; p++) {
        int idx = tid + p * 320;
        if (idx < 32 * 45) {
            int k = idx / 45, c45 = idx - k * 45;
            qk_[p] = k; qso_[p] = k * VQ_ + c45 * 2; qdo_[p] = k * 104 + c45 * 2;
        } else qk_[p] = -1;
    }
    int kk_[3], kso_[3], kdo_[3];
    #pragma unroll
    for (int p = 0; p < 3; p++) {
        int idx = tid + p * 320;
        if (idx < 36 * 25) {
            int k = idx / 25, c25 = idx - k * 25;
            kk_[p] = k; kso_[p] = k * VK_ + c25 * 2; kdo_[p] = SC_BUF_Q + k * 72 + c25 * 2;
        } else kk_[p] = -1;
    }

    auto issue = [&](int it) {
        const int c = ksb * CPB + (it >> 3), tt = it & 7;
        const int t0 = tt * 32;
        const int kw = (tt == 7) ? 28 : 32;
        const int krows = (tt == 7) ? 32 : 36;
        const u32 base = smem0 + (u32)(it & 3) * (SC_BUF * 4);
        const float* Qsrc = Qb + (long)c * SPQ + (long)t0 * VQ_;
        const float* Ksrc = Kb + (long)c * SPK + (long)t0 * VK_;
        #pragma unroll
        for (int p = 0; p < 5; p++) {
            if (qk_[p] >= 0) {
                u32 sz = (qk_[p] < kw) ? 8u : 0u;
                cpa8(base + qdo_[p] * 4, sz ? (Qsrc + qso_[p]) : Qb, sz);
            }
        }
        #pragma unroll
        for (int p = 0; p < 3; p++) {
            if (kk_[p] >= 0) {
                u32 sz = (kk_[p] < krows) ? 8u : 0u;
                cpa8(base + kdo_[p] * 4, sz ? (Ksrc + kso_[p]) : Kb, sz);
            }
        }
        cpa_commit();
    };

    float acc[3][7][4];
    #pragma unroll
    for (int i = 0; i < 3; i++)
        #pragma unroll
        for (int j = 0; j < 7; j++)
            #pragma unroll
            for (int e = 0; e < 4; e++) acc[i][j][e] = 0.f;

    const int NT = CPB * 8;
    issue(0); issue(1); issue(2);

    for (int it = 0; it < NT; it++) {
        int rem = NT - it - 1; rem = rem > 2 ? 2 : rem;
        if (rem == 2) cpa_wait2(); else if (rem == 1) cpa_wait1(); else cpa_wait0();
        __syncthreads();
        if (it + 3 < NT) issue(it + 3);
        const u32* Qsb = sdyn + (it & 3) * SC_BUF;
        const u32* Ksb = Qsb + SC_BUF_Q;
        #pragma unroll
        for (int k8 = 0; k8 < 4; k8++) {
            const int k0 = k8 * 8;
            u32 a[3][4], b[7][2];
            #pragma unroll
            for (int i = 0; i < 3; i++) {
                int u = uh * 48 + i * 16 + g;
                a[i][0] = tf32s(Qsb[(k0 + tg) * 104 + u]);
                a[i][1] = tf32s(Qsb[(k0 + tg) * 104 + u + 8]);
                a[i][2] = tf32s(Qsb[(k0 + tg + 4) * 104 + u]);
                a[i][3] = tf32s(Qsb[(k0 + tg + 4) * 104 + u + 8]);
            }
            #pragma unroll
            for (int j = 0; j < 7; j++) {
                b[j][0] = tf32s(Ksb[(k0 + tg + l) * 72 + j * 8 + g]);
                b[j][1] = tf32s(Ksb[(k0 + tg + 4 + l) * 72 + j * 8 + g]);
            }
            #pragma unroll
            for (int i = 0; i < 3; i++)
                #pragma unroll
                for (int j = 0; j < 7; j++) mma8(acc[i][j], a[i], b[j]);
        }
        __syncthreads();
    }

    float* pb = part + (((long)ksb * NS_ + ns) * 5 + l) * (VQ_ * VK_);
    #pragma unroll
    for (int i = 0; i < 3; i++) {
        #pragma unroll
        for (int j = 0; j < 7; j++) {
            int u = uh * 48 + i * 16 + g;
            int v = j * 8 + 2 * tg;
            if (v < VK_) {
                if (u < VQ_) {
                    pb[u * VK_ + v]     = acc[i][j][0];
                    pb[u * VK_ + v + 1] = acc[i][j][1];
                }
                if (u + 8 < VQ_) {
                    pb[(u + 8) * VK_ + v]     = acc[i][j][2];
                    pb[(u + 8) * VK_ + v + 1] = acc[i][j][3];
                }
            }
        }
    }
}

// ---------------- combine lags + softmax over VK -----------------------------
__global__ __launch_bounds__(64)
void softmax_kernel(const float* __restrict__ part, float* __restrict__ att)
{
    const int row = blockIdx.x;
    const int ns = row / VQ_;
    const int u  = row - ns * VQ_;
    const int tid = threadIdx.x;
    const float inv_scale = rsqrtf((float)KTOT);

    __shared__ float red[64];
    float val = -1e30f;
    if (tid < VK_) {
        float mx = -1e30f, sm = 0.f;
        #pragma unroll
        for (int l = 0; l <= L_; l++) {
            float s = 0.f;
            #pragma unroll
            for (int ks = 0; ks < KSPLIT; ks++)
                s += part[((((long)ks * NS_ + ns) * 5 + l) * VQ_ + u) * VK_ + tid];
            mx = fmaxf(mx, s);
            sm += s;
        }
        val = 0.5f * (mx + sm * 0.2f) * inv_scale;
    }
    red[tid] = val; __syncthreads();
    for (int s = 32; s > 0; s >>= 1) {
        if (tid < s) red[tid] = fmaxf(red[tid], red[tid + s]);
        __syncthreads();
    }
    float rmax = red[0]; __syncthreads();
    float e = (tid < VK_) ? expf(val - rmax) : 0.f;
    red[tid] = e; __syncthreads();
    for (int s = 32; s > 0; s >>= 1) {
        if (tid < s) red[tid] += red[tid + s];
        __syncthreads();
    }
    float rsum = red[0];
    if (tid < VK_) att[(long)row * VK_ + tid] = e / rsum;
}

// ---------------- y = att @ V, 4 s-values per block (V staged once) ----------
#define YG_SMEM ((56*136 + 56*104) * 4)
__global__ __launch_bounds__(256)
void ygemm_mma(const float* __restrict__ Vp, const float* __restrict__ att,
               float* __restrict__ y)
{
    extern __shared__ u32 dynsh[];
    u32* Vs = dynsh;            // [k][ct] stride 136
    u32* Bs = dynsh + 56 * 136; // [k][vq] stride 104

    const int ct0 = blockIdx.x * 128;
    const int n   = blockIdx.y;
    const float* A = Vp + (long)n * VP_PER_N + (long)ct0 * VK_;

    const int tid = threadIdx.x, w = tid >> 5, lane = tid & 31;
    const int g = lane >> 2, tg = lane & 3;
    const int mw = (w & 3) * 32, nw = (w >> 2) * 48;

    for (int idx = tid; idx < 128 * 56; idx += 256) {
        int ct = idx / 56, k = idx - (idx / 56) * 56;
        Vs[k * 136 + ct] = (k < VK_) ? tf32u(A[ct * VK_ + k]) : 0u;
    }

    for (int s = 0; s < 4; s++) {
        const float* B = att + (long)(n * 4 + s) * (VQ_ * VK_);
        float* Yb = y + (long)(n * 4 + s) * Y_PER_NS;
        for (int idx = tid; idx < 96 * 56; idx += 256) {
            int vq = idx / 56, k = idx - (idx / 56) * 56;
            Bs[k * 104 + vq] = (k < VK_ && vq < VQ_) ? tf32u(B[vq * VK_ + k]) : 0u;
        }
        __syncthreads();

        float acc[2][6][4];
        #pragma unroll
        for (int i = 0; i < 2; i++)
            #pragma unroll
            for (int j = 0; j < 6; j++)
                #pragma unroll
                for (int e = 0; e < 4; e++) acc[i][j][e] = 0.f;

        #pragma unroll
        for (int kq = 0; kq < 7; kq++) {
            const int k0 = kq * 8;
            u32 a[2][4];
            #pragma unroll
            for (int mi = 0; mi < 2; mi++) {
                int m = mw + mi * 16;
                a[mi][0] = Vs[(k0 + tg) * 136 + m + g];
                a[mi][1] = Vs[(k0 + tg) * 136 + m + g + 8];
                a[mi][2] = Vs[(k0 + tg + 4) * 136 + m + g];
                a[mi][3] = Vs[(k0 + tg + 4) * 136 + m + g + 8];
            }
            #pragma unroll
            for (int ji = 0; ji < 6; ji++) {
                u32 b[2];
                b[0] = Bs[(k0 + tg) * 104 + nw + ji * 8 + g];
                b[1] = Bs[(k0 + tg + 4) * 104 + nw + ji * 8 + g];
                mma8(acc[0][ji], a[0], b);
                mma8(acc[1][ji], a[1], b);
            }
        }
        #pragma unroll
        for (int mi = 0; mi < 2; mi++) {
            int ct = ct0 + mw + mi * 16 + g;
            #pragma unroll
            for (int ji = 0; ji < 6; ji++) {
                int vq = nw + ji * 8 + 2 * tg;
                if (vq < VQ_) {
                    float2 o0; o0.x = acc[mi][ji][0]; o0.y = acc[mi][ji][1];
                    float2 o1; o1.x = acc[mi][ji][2]; o1.y = acc[mi][ji][3];
                    *(float2*)&Yb[(long)ct * VQ_ + vq] = o0;
                    *(float2*)&Yb[(long)(ct + 8) * VQ_ + vq] = o1;
                }
            }
        }
        __syncthreads();   // all reads of Bs done before restage
    }
}

// ---------------- BN finalize from per-block partials ------------------------
__global__ __launch_bounds__(256)
void bn_final(const float* __restrict__ partials,
              const float* __restrict__ gz, const float* __restrict__ bz,
              const float* __restrict__ gd, const float* __restrict__ bd,
              float* __restrict__ coef)
{
    const int which = blockIdx.x;          // 0 = z(out), 1 = d(down)
    const int tid = threadIdx.x;
    const int c = tid & 63, q = tid >> 6;  // 4 chunks of 180 blocks
    const float2* p = (const float2*)partials + (long)which * NBLK_BN * 64;

    float a0 = 0.f, a1 = 0.f, b0 = 0.f, b1 = 0.f;
    for (int bb = 0; bb < 180; bb += 2) {
        float2 v0 = p[(long)(q * 180 + bb) * 64 + c];
        float2 v1 = p[(long)(q * 180 + bb + 1) * 64 + c];
        a0 += v0.x; b0 += v0.y;
        a1 += v1.x; b1 += v1.y;
    }
    __shared__ float r1[256], r2[256];
    r1[tid] = a0 + a1; r2[tid] = b0 + b1;
    __syncthreads();
    if (q == 0) {
        float s1 = r1[c] + r1[64 + c] + r1[128 + c] + r1[192 + c];
        float s2 = r2[c] + r2[64 + c] + r2[128 + c] + r2[192 + c];
        float inv = 1.0f / (float)BN_COUNT;
        float mean = s1 * inv;
        float var  = s2 * inv - mean * mean;
        float rstd = rsqrtf(var + 1e-5f);
        float gm = which ? gd[c] : gz[c];
        float bt = which ? bd[c] : bz[c];
        float a = gm * rstd;
        coef[(which * 64 + c) * 2 + 0] = a;
        coef[(which * 64 + c) * 2 + 1] = bt - mean * a;
    }
}

// ---------------- final: leaky_relu(bn(d) + bn(z)), float4 -------------------
__global__ __launch_bounds__(256)
void final_kernel(const float* __restrict__ z, const float* __restrict__ d,
                  const float* __restrict__ coef, float* __restrict__ out)
{
    long i4 = ((long)blockIdx.x * 256 + threadIdx.x) * 4;
    if (i4 >= OUT_TOTAL) return;
    int c = (int)((i4 / SPO) & (C_ - 1));
    float az = coef[c * 2], bz_ = coef[c * 2 + 1];
    float ad = coef[(C_ + c) * 2], bd_ = coef[(C_ + c) * 2 + 1];
    float4 zv = *(const float4*)&z[i4];
    float4 dv = *(const float4*)&d[i4];
    float4 o;
    float v;
    v = fmaf(az, zv.x, bz_) + fmaf(ad, dv.x, bd_); o.x = v > 0.f ? v : 0.1f * v;
    v = fmaf(az, zv.y, bz_) + fmaf(ad, dv.y, bd_); o.y = v > 0.f ? v : 0.1f * v;
    v = fmaf(az, zv.z, bz_) + fmaf(ad, dv.z, bd_); o.z = v > 0.f ? v : 0.1f * v;
    v = fmaf(az, zv.w, bz_) + fmaf(ad, dv.w, bd_); o.w = v > 0.f ? v : 0.1f * v;
    *(float4*)&out[i4] = o;
}

// ---------------- launch -----------------------------------------------------
extern "C" void kernel_launch(void* const* d_in, const int* in_sizes, int n_in,
                              void* d_out, int out_size)
{
    const float* x_q   = (const float*)d_in[0];
    const float* x_k   = (const float*)d_in[1];
    const float* x_v   = (const float*)d_in[2];
    const float* Wq    = (const float*)d_in[3];
    const float* bq    = (const float*)d_in[4];
    const float* Wk    = (const float*)d_in[5];
    const float* bk    = (const float*)d_in[6];
    const float* Wv    = (const float*)d_in[7];
    const float* bv    = (const float*)d_in[8];
    const float* Wout  = (const float*)d_in[9];
    const float* bout  = (const float*)d_in[10];
    const float* gout  = (const float*)d_in[11];
    const float* bnout = (const float*)d_in[12];
    const float* Wdown = (const float*)d_in[13];
    const float* bdown = (const float*)d_in[14];
    const float* gdown = (const float*)d_in[15];
    const float* bndwn = (const float*)d_in[16];

    float *Qp, *Kp, *Vp, *part, *att, *y, *z, *dd, *bnp2, *coef;
    cudaGetSymbolAddress((void**)&Qp,   g_Qp);
    cudaGetSymbolAddress((void**)&Kp,   g_Kp);
    cudaGetSymbolAddress((void**)&Vp,   g_Vp);
    cudaGetSymbolAddress((void**)&part, g_part);
    cudaGetSymbolAddress((void**)&att,  g_att);
    cudaGetSymbolAddress((void**)&y,    g_y);
    cudaGetSymbolAddress((void**)&z,    g_z);
    cudaGetSymbolAddress((void**)&dd,   g_d);
    cudaGetSymbolAddress((void**)&bnp2, g_bnp2);
    cudaGetSymbolAddress((void**)&coef, g_bncoef);

    cudaFuncSetAttribute(conv_mma,  cudaFuncAttributeMaxDynamicSharedMemorySize, CONV_SMEM);
    cudaFuncSetAttribute(score_mma, cudaFuncAttributeMaxDynamicSharedMemorySize, SC_SMEM);
    cudaFuncSetAttribute(ygemm_mma, cudaFuncAttributeMaxDynamicSharedMemorySize, YG_SMEM);

    // projections (tensor-core, cp.async pipelined); Wdown emits BN partials
    conv_mma<<<dim3(89, 4, N_), 256, CONV_SMEM>>>(Wq, bq, x_q, Qp, 256, 64, SPQ, SPO, 1474560L, 5806080L, nullptr);
    conv_mma<<<dim3(50, 4, N_), 256, CONV_SMEM>>>(Wk, bk, x_k, Kp, 256, 64, SPK, SPK, 819200L, 3276800L, nullptr);
    conv_mma<<<dim3(50, 1, N_), 256, CONV_SMEM>>>(Wv, bv, x_v, Vp, 64, 64, SPK, SPK, 819200L, 819200L, nullptr);
    conv_mma<<<dim3(90, 1, N_), 256, CONV_SMEM>>>(Wdown, bdown, x_q, dd, 64, 64, SPO, SPO, 1474560L, 1474560L,
                                                  bnp2 + 2L * NBLK_BN * 64);

    // tensor-core multi-lag scores + softmax
    score_mma<<<dim3(NS_, KSPLIT), 320, SC_SMEM>>>(Qp, Kp, part);
    softmax_kernel<<<NS_ * VQ_, 64>>>(part, att);

    // y = att @ V (4 s per block), out projection (emits BN partials)
    ygemm_mma<<<dim3(128, N_), 256, YG_SMEM>>>(Vp, att, y);
    conv_mma<<<dim3(90, 1, N_), 256, CONV_SMEM>>>(Wout, bout, y, z, 64, 256, SPO, SPO, 5898240L, 1474560L, bnp2);

    // BN finalize + fused epilogue
    bn_final<<<2, 256>>>(bnp2, gout, bnout, gdown, bndwn, coef);
    final_kernel<<<(OUT_TOTAL / 4 + 255) / 256, 256>>>(z, dd, coef, (float*)d_out);
}